// round 5
// baseline (speedup 1.0000x reference)
#include <cuda_runtime.h>
#include <cstddef>

#define DEVF __device__ __forceinline__
typedef unsigned long long ull;

// ---------------- scratch (device globals; no allocations allowed) ----------
__device__ float g_q  [3200 * 512];
__device__ float g_k  [12288 * 512];
__device__ float g_v  [12288 * 512];
__device__ float g_ctx[3200 * 512];
__device__ float g_x1 [3200 * 512];
__device__ float g_x2 [3200 * 512];
__device__ float g_tmp[3200 * 512];
__device__ float g_yt [3200 * 512];

// LSTM wavefront buffers: Y[l][t][k][b], l = 0..32, t<512, k<25, b<128
#define YSTRIDE 1638400   // 512*25*128
__device__ float g_Y[33ull * YSTRIDE];
__device__ int   g_flags[33 * 4 * 32];   // (layer,chunk) progress, 128B padded

// ---------------- f32x2 packed helpers ---------------------------------------
DEVF void fma2(ull& d, ull a, ull b) {
    asm("fma.rn.f32x2 %0, %1, %2, %0;" : "+l"(d) : "l"(a), "l"(b));
}
DEVF ull splat2(float x) {
    ull r; unsigned ix = __float_as_uint(x);
    asm("mov.b64 %0, {%1, %1};" : "=l"(r) : "r"(ix));
    return r;
}
DEVF float2 unpack2(ull v) {
    unsigned lo, hi;
    asm("mov.b64 {%0, %1}, %2;" : "=r"(lo), "=r"(hi) : "l"(v));
    return make_float2(__uint_as_float(lo), __uint_as_float(hi));
}

// ---------------- activations ------------------------------------------------
DEVF float fsig(float x) { return 1.f / (1.f + __expf(-x)); }
DEVF float ftanh(float x) {
    float ax = fabsf(x);
    float e  = __expf(-2.f * ax);
    float t  = __fdividef(1.f - e, 1.f + e);
    return copysignf(t, x);
}

// ---------------- GEMM: 64x64 tile, 128 threads, double-buffered, f32x2 ------
// C[.,512] = A[.,512] @ W (+bias)(+res). TRANSW: W stored [N,K] else [K,N].
template<bool TRANSW>
DEVF void gemm_core(const float* __restrict__ A, const float* __restrict__ W,
                    const float* __restrict__ bias, const float* __restrict__ res,
                    float* __restrict__ C)
{
    __shared__ __align__(16) float As[2][16][64];
    __shared__ __align__(16) float Bs[2][16][64];
    int tid = threadIdx.x;
    int bm = blockIdx.x * 64, bn = blockIdx.y * 64;
    int tx = tid & 15, ty = tid >> 4;

    ull acc[4][4];
    #pragma unroll
    for (int i = 0; i < 4; i++)
        #pragma unroll
        for (int j = 0; j < 4; j++) acc[i][j] = 0ull;

    int ar = tid >> 1;           // 0..63
    int ac = (tid & 1) * 8;      // 0 or 8
    const float* Arow = A + (size_t)(bm + ar) * 512 + ac;

    int b_kk = tid >> 3, b_nn = (tid & 7) * 8;    // !TRANSW
    int b_n2 = tid >> 1, b_k2 = (tid & 1) * 8;    // TRANSW

    float4 a0, a1, bv0, bv1;
    a0 = *(const float4*)(Arow + 0);
    a1 = *(const float4*)(Arow + 4);
    if (!TRANSW) {
        bv0 = *(const float4*)(W + (size_t)b_kk * 512 + bn + b_nn);
        bv1 = *(const float4*)(W + (size_t)b_kk * 512 + bn + b_nn + 4);
    } else {
        bv0 = *(const float4*)(W + (size_t)(bn + b_n2) * 512 + b_k2);
        bv1 = *(const float4*)(W + (size_t)(bn + b_n2) * 512 + b_k2 + 4);
    }
    As[0][ac + 0][ar] = a0.x; As[0][ac + 1][ar] = a0.y;
    As[0][ac + 2][ar] = a0.z; As[0][ac + 3][ar] = a0.w;
    As[0][ac + 4][ar] = a1.x; As[0][ac + 5][ar] = a1.y;
    As[0][ac + 6][ar] = a1.z; As[0][ac + 7][ar] = a1.w;
    if (!TRANSW) {
        *(float4*)&Bs[0][b_kk][b_nn]     = bv0;
        *(float4*)&Bs[0][b_kk][b_nn + 4] = bv1;
    } else {
        Bs[0][b_k2 + 0][b_n2] = bv0.x; Bs[0][b_k2 + 1][b_n2] = bv0.y;
        Bs[0][b_k2 + 2][b_n2] = bv0.z; Bs[0][b_k2 + 3][b_n2] = bv0.w;
        Bs[0][b_k2 + 4][b_n2] = bv1.x; Bs[0][b_k2 + 5][b_n2] = bv1.y;
        Bs[0][b_k2 + 6][b_n2] = bv1.z; Bs[0][b_k2 + 7][b_n2] = bv1.w;
    }
    __syncthreads();

    for (int it = 0; it < 32; it++) {
        int buf = it & 1;
        if (it < 31) {
            int k0 = (it + 1) * 16;
            a0 = *(const float4*)(Arow + k0);
            a1 = *(const float4*)(Arow + k0 + 4);
            if (!TRANSW) {
                bv0 = *(const float4*)(W + (size_t)(k0 + b_kk) * 512 + bn + b_nn);
                bv1 = *(const float4*)(W + (size_t)(k0 + b_kk) * 512 + bn + b_nn + 4);
            } else {
                bv0 = *(const float4*)(W + (size_t)(bn + b_n2) * 512 + k0 + b_k2);
                bv1 = *(const float4*)(W + (size_t)(bn + b_n2) * 512 + k0 + b_k2 + 4);
            }
        }
        #pragma unroll
        for (int k = 0; k < 16; k++) {
            ulonglong2 a01 = *(const ulonglong2*)&As[buf][k][ty * 8];
            ulonglong2 a23 = *(const ulonglong2*)&As[buf][k][ty * 8 + 4];
            float4 b4 = *(const float4*)&Bs[buf][k][tx * 4];
            ull bs0 = splat2(b4.x), bs1 = splat2(b4.y);
            ull bs2 = splat2(b4.z), bs3 = splat2(b4.w);
            fma2(acc[0][0], a01.x, bs0); fma2(acc[0][1], a01.x, bs1);
            fma2(acc[0][2], a01.x, bs2); fma2(acc[0][3], a01.x, bs3);
            fma2(acc[1][0], a01.y, bs0); fma2(acc[1][1], a01.y, bs1);
            fma2(acc[1][2], a01.y, bs2); fma2(acc[1][3], a01.y, bs3);
            fma2(acc[2][0], a23.x, bs0); fma2(acc[2][1], a23.x, bs1);
            fma2(acc[2][2], a23.x, bs2); fma2(acc[2][3], a23.x, bs3);
            fma2(acc[3][0], a23.y, bs0); fma2(acc[3][1], a23.y, bs1);
            fma2(acc[3][2], a23.y, bs2); fma2(acc[3][3], a23.y, bs3);
        }
        if (it < 31) {
            int nb = buf ^ 1;
            As[nb][ac + 0][ar] = a0.x; As[nb][ac + 1][ar] = a0.y;
            As[nb][ac + 2][ar] = a0.z; As[nb][ac + 3][ar] = a0.w;
            As[nb][ac + 4][ar] = a1.x; As[nb][ac + 5][ar] = a1.y;
            As[nb][ac + 6][ar] = a1.z; As[nb][ac + 7][ar] = a1.w;
            if (!TRANSW) {
                *(float4*)&Bs[nb][b_kk][b_nn]     = bv0;
                *(float4*)&Bs[nb][b_kk][b_nn + 4] = bv1;
            } else {
                Bs[nb][b_k2 + 0][b_n2] = bv0.x; Bs[nb][b_k2 + 1][b_n2] = bv0.y;
                Bs[nb][b_k2 + 2][b_n2] = bv0.z; Bs[nb][b_k2 + 3][b_n2] = bv0.w;
                Bs[nb][b_k2 + 4][b_n2] = bv1.x; Bs[nb][b_k2 + 5][b_n2] = bv1.y;
                Bs[nb][b_k2 + 6][b_n2] = bv1.z; Bs[nb][b_k2 + 7][b_n2] = bv1.w;
            }
        }
        __syncthreads();
    }

    float4 bv4 = *(const float4*)(bias + bn + tx * 4);
    float bb[4] = {bv4.x, bv4.y, bv4.z, bv4.w};
    #pragma unroll
    for (int mp = 0; mp < 4; mp++) {
        int m = bm + ty * 8 + mp * 2;
        float r0[4], r1[4];
        #pragma unroll
        for (int n = 0; n < 4; n++) {
            float2 f = unpack2(acc[mp][n]);
            r0[n] = f.x + bb[n];
            r1[n] = f.y + bb[n];
        }
        if (res) {
            float4 q0 = *(const float4*)(res + (size_t)m * 512 + bn + tx * 4);
            float4 q1 = *(const float4*)(res + (size_t)(m + 1) * 512 + bn + tx * 4);
            r0[0] += q0.x; r0[1] += q0.y; r0[2] += q0.z; r0[3] += q0.w;
            r1[0] += q1.x; r1[1] += q1.y; r1[2] += q1.z; r1[3] += q1.w;
        }
        *(float4*)(C + (size_t)m * 512 + bn + tx * 4) = make_float4(r0[0], r0[1], r0[2], r0[3]);
        *(float4*)(C + (size_t)(m + 1) * 512 + bn + tx * 4) = make_float4(r1[0], r1[1], r1[2], r1[3]);
    }
}

struct GemmSet {
    const float* W[3];
    const float* b[3];
    const float* r[3];
    float*       C[3];
};

template<bool TRANSW>
__global__ void __launch_bounds__(128, 5) gemm_db_kernel(const float* __restrict__ A, GemmSet s) {
    int z = blockIdx.z;
    gemm_core<TRANSW>(A, s.W[z], s.b[z], s.r[z], s.C[z]);
}

// ---------------- attention core: one block per (b, h), 256 threads ---------
__global__ void __launch_bounds__(256) attn_kernel(
    const float* __restrict__ Q, const float* __restrict__ Kp,
    const float* __restrict__ Vp, float* __restrict__ O, int S)
{
    __shared__ float qs[25 * 64];
    __shared__ float kv[96 * 64];
    __shared__ float sc[25 * 96];
    int b = blockIdx.x >> 3, h = blockIdx.x & 7;
    int tid = threadIdx.x;
    const float scale = 0.125f;
    size_t qbase = (size_t)b * 25 * 512 + h * 64;
    size_t kbase = (size_t)b * S  * 512 + h * 64;

    for (int i = tid; i < 25 * 64; i += 256) qs[i] = Q[qbase + (size_t)(i >> 6) * 512 + (i & 63)];
    for (int i = tid; i < S  * 64; i += 256) kv[i] = Kp[kbase + (size_t)(i >> 6) * 512 + (i & 63)];
    __syncthreads();

    for (int i = tid; i < 25 * S; i += 256) {
        int l = i / S, s = i - l * S;
        float acc = 0.f;
        #pragma unroll 16
        for (int e = 0; e < 64; e++) acc += qs[l * 64 + e] * kv[s * 64 + e];
        sc[i] = acc * scale;
    }
    __syncthreads();

    int warp = tid >> 5, lane = tid & 31;
    for (int l = warp; l < 25; l += 8) {
        float mx = -1e30f;
        for (int s = lane; s < S; s += 32) mx = fmaxf(mx, sc[l * S + s]);
        #pragma unroll
        for (int o = 16; o; o >>= 1) mx = fmaxf(mx, __shfl_xor_sync(~0u, mx, o));
        float sum = 0.f;
        for (int s = lane; s < S; s += 32) {
            float e = __expf(sc[l * S + s] - mx);
            sc[l * S + s] = e; sum += e;
        }
        #pragma unroll
        for (int o = 16; o; o >>= 1) sum += __shfl_xor_sync(~0u, sum, o);
        float inv = __fdividef(1.f, sum);
        for (int s = lane; s < S; s += 32) sc[l * S + s] *= inv;
    }
    __syncthreads();

    for (int i = tid; i < S * 64; i += 256) kv[i] = Vp[kbase + (size_t)(i >> 6) * 512 + (i & 63)];
    __syncthreads();

    for (int i = tid; i < 25 * 64; i += 256) {
        int l = i >> 6, e = i & 63;
        float acc = 0.f;
        for (int s = 0; s < S; s++) acc += sc[l * S + s] * kv[s * 64 + e];
        O[qbase + (size_t)l * 512 + e] = acc;
    }
}

// ---------------- LayerNorm over rows of 512 (warp per row) ------------------
__global__ void __launch_bounds__(256) ln_kernel(
    const float* __restrict__ in, const float* __restrict__ g,
    const float* __restrict__ bb, float* __restrict__ out, int M)
{
    int row = blockIdx.x * 8 + (threadIdx.x >> 5);
    int lane = threadIdx.x & 31;
    if (row >= M) return;
    const float* p = in + (size_t)row * 512;
    float v[16];
    float s = 0.f, s2 = 0.f;
    #pragma unroll
    for (int i = 0; i < 16; i++) {
        v[i] = p[lane + 32 * i];
        s += v[i]; s2 += v[i] * v[i];
    }
    #pragma unroll
    for (int o = 16; o; o >>= 1) {
        s  += __shfl_xor_sync(~0u, s,  o);
        s2 += __shfl_xor_sync(~0u, s2, o);
    }
    float mean = s * (1.f / 512.f);
    float var  = s2 * (1.f / 512.f) - mean * mean;
    float rstd = rsqrtf(var + 1e-5f);
    float* q = out + (size_t)row * 512;
    #pragma unroll
    for (int i = 0; i < 16; i++) {
        int d = lane + 32 * i;
        q[d] = (v[i] - mean) * rstd * g[d] + bb[d];
    }
}

// ---------------- tiled transposes -------------------------------------------
// in x2 [b][l=k][d=t] -> Y0 [t][k][b]   (both sides coalesced via smem tile)
__global__ void transpose_in_kernel(const float* __restrict__ in, float* __restrict__ out) {
    __shared__ float tile[32][33];
    int tx = threadIdx.x, ty = threadIdx.y;
    int t0 = blockIdx.x * 32, b0 = blockIdx.y * 32, k = blockIdx.z;
    #pragma unroll
    for (int i = 0; i < 4; i++)
        tile[ty + 8 * i][tx] = in[(size_t)(b0 + ty + 8 * i) * 12800 + k * 512 + t0 + tx];
    __syncthreads();
    #pragma unroll
    for (int i = 0; i < 4; i++)
        out[(size_t)(t0 + ty + 8 * i) * 3200 + k * 128 + b0 + tx] = tile[tx][ty + 8 * i];
}
// in Y32 [c][l][b] -> yt [(b,l)][c]
__global__ void transpose_out_kernel(const float* __restrict__ in, float* __restrict__ out) {
    __shared__ float tile[32][33];
    int tx = threadIdx.x, ty = threadIdx.y;
    int c0 = blockIdx.x * 32, b0 = blockIdx.y * 32, l = blockIdx.z;
    #pragma unroll
    for (int i = 0; i < 4; i++)
        tile[ty + 8 * i][tx] = in[(size_t)(c0 + ty + 8 * i) * 3200 + l * 128 + b0 + tx];
    __syncthreads();
    #pragma unroll
    for (int i = 0; i < 4; i++)
        out[(size_t)((b0 + ty + 8 * i) * 25 + l) * 512 + c0 + tx] = tile[tx][ty + 8 * i];
}

__global__ void zero_flags_kernel() {
    int i = blockIdx.x * 256 + threadIdx.x;
    if (i < 33 * 4 * 32) g_flags[i] = 0;
}

DEVF void spinwait(const int* p, int need) {
    int v;
    do {
        asm volatile("ld.acquire.gpu.global.b32 %0, [%1];" : "=r"(v) : "l"(p) : "memory");
    } while (v < need);
}

// ---------------- LSTM wavefront: 128 blocks = 32 layers x 4 chunks ----------
// 512 threads. Warps 8-14 (high wid = arbiter priority): recurrent h-part +
// activations + state update (critical path). Warps 0-6: precompute
// pre[t+1] = x_{t+1} @ W_ih + bias. Warp 7: flag wait + x prefetch (2 ahead).
// Gates are written in-place into the pre buffer. 2 barriers/step.
__global__ void __launch_bounds__(512) lstm_wave_kernel(
    const float* __restrict__ Wih, const float* __restrict__ Whh,
    const float* __restrict__ bih, const float* __restrict__ bhh)
{
    int layer = blockIdx.x & 31;
    int chunk = blockIdx.x >> 5;
    int b0 = chunk * 32;
    const float* in  = g_Y + (size_t)layer * YSTRIDE;
    float* outp      = g_Y + (size_t)(layer + 1) * YSTRIDE;
    const int* inflag = g_flags + (layer * 4 + chunk) * 32;
    int* outflag      = g_flags + ((layer + 1) * 4 + chunk) * 32;

    __shared__ __align__(16) float pre [2][100][32];   // pre-gates; gates in-place
    __shared__ __align__(16) float xbuf[2][25][32];
    __shared__ __align__(16) float hbuf[25][32];

    int tid = threadIdx.x;
    bool isRec = (tid >= 256 && tid < 456);
    bool isPre = (tid < 200);
    bool isIO  = (tid >= 224 && tid < 256);
    int idx = isRec ? (tid - 256) : tid;
    int j = idx >> 1, bbase = (idx & 1) << 4;

    ull wsp[25];     // splatted weights: Whh row (rec) or Wih row (pre)
    ull bias2 = 0ull;
    if (isPre) {
        const float* wi = Wih + (size_t)layer * 2500 + j * 25;
        #pragma unroll
        for (int k = 0; k < 25; k++) wsp[k] = splat2(wi[k]);
        bias2 = splat2(bih[layer * 100 + j] + bhh[layer * 100 + j]);
    } else if (isRec) {
        const float* wh = Whh + (size_t)layer * 2500 + j * 25;
        #pragma unroll
        for (int k = 0; k < 25; k++) wsp[k] = splat2(wh[k]);
    }
    int u = idx >> 3, bb = (idx & 7) << 2;
    float4 cst = make_float4(0.f, 0.f, 0.f, 0.f);
    bool isg = (j >= 50 && j < 75);

    for (int i = tid; i < 800; i += 512) hbuf[i >> 5][i & 31] = 0.f;

    // prologue: x_0 -> xbuf[0], x_1 -> xbuf[1]; pre[0] from x_0
    if (isIO) {
        if (layer > 0 && tid == 224) spinwait(inflag, 2);
        __syncwarp();
        int lane = tid - 224;
        #pragma unroll
        for (int k = 0; k < 25; k++) {
            xbuf[0][k][lane] = in[k * 128 + b0 + lane];
            xbuf[1][k][lane] = in[3200 + k * 128 + b0 + lane];
        }
    }
    __syncthreads();
    if (isPre) {
        ull acc[8];
        #pragma unroll
        for (int q = 0; q < 8; q++) acc[q] = bias2;
        #pragma unroll
        for (int k = 0; k < 25; k++) {
            ull wp = wsp[k];
            const ulonglong2* row = (const ulonglong2*)&xbuf[0][k][bbase];
            ulonglong2 p0 = row[0], p1 = row[1], p2 = row[2], p3 = row[3];
            fma2(acc[0], p0.x, wp); fma2(acc[1], p0.y, wp);
            fma2(acc[2], p1.x, wp); fma2(acc[3], p1.y, wp);
            fma2(acc[4], p2.x, wp); fma2(acc[5], p2.y, wp);
            fma2(acc[6], p3.x, wp); fma2(acc[7], p3.y, wp);
        }
        ulonglong2* dst = (ulonglong2*)&pre[0][j][bbase];
        dst[0] = make_ulonglong2(acc[0], acc[1]);
        dst[1] = make_ulonglong2(acc[2], acc[3]);
        dst[2] = make_ulonglong2(acc[4], acc[5]);
        dst[3] = make_ulonglong2(acc[6], acc[7]);
    }
    __syncthreads();

    for (int t = 0; t < 512; t++) {
        int par = t & 1;
        // phase A
        if (isRec) {
            const ulonglong2* pr = (const ulonglong2*)&pre[par][j][bbase];
            ulonglong2 i0 = pr[0], i1 = pr[1], i2 = pr[2], i3 = pr[3];
            ull acc[8] = {i0.x, i0.y, i1.x, i1.y, i2.x, i2.y, i3.x, i3.y};
            #pragma unroll
            for (int k = 0; k < 25; k++) {
                ull wp = wsp[k];
                const ulonglong2* row = (const ulonglong2*)&hbuf[k][bbase];
                ulonglong2 p0 = row[0], p1 = row[1], p2 = row[2], p3 = row[3];
                fma2(acc[0], p0.x, wp); fma2(acc[1], p0.y, wp);
                fma2(acc[2], p1.x, wp); fma2(acc[3], p1.y, wp);
                fma2(acc[4], p2.x, wp); fma2(acc[5], p2.y, wp);
                fma2(acc[6], p3.x, wp); fma2(acc[7], p3.y, wp);
            }
            float g16[16];
            #pragma unroll
            for (int q = 0; q < 8; q++) {
                float2 f = unpack2(acc[q]);
                g16[2 * q] = f.x; g16[2 * q + 1] = f.y;
            }
            #pragma unroll
            for (int i = 0; i < 16; i++) g16[i] = isg ? ftanh(g16[i]) : fsig(g16[i]);
            float4* gp = (float4*)&pre[par][j][bbase];
            gp[0] = make_float4(g16[0],  g16[1],  g16[2],  g16[3]);
            gp[1] = make_float4(g16[4],  g16[5],  g16[6],  g16[7]);
            gp[2] = make_float4(g16[8],  g16[9],  g16[10], g16[11]);
            gp[3] = make_float4(g16[12], g16[13], g16[14], g16[15]);
        } else if (isPre) {
            if (t < 511) {
                int xp = (t + 1) & 1;
                ull acc[8];
                #pragma unroll
                for (int q = 0; q < 8; q++) acc[q] = bias2;
                #pragma unroll
                for (int k = 0; k < 25; k++) {
                    ull wp = wsp[k];
                    const ulonglong2* row = (const ulonglong2*)&xbuf[xp][k][bbase];
                    ulonglong2 p0 = row[0], p1 = row[1], p2 = row[2], p3 = row[3];
                    fma2(acc[0], p0.x, wp); fma2(acc[1], p0.y, wp);
                    fma2(acc[2], p1.x, wp); fma2(acc[3], p1.y, wp);
                    fma2(acc[4], p2.x, wp); fma2(acc[5], p2.y, wp);
                    fma2(acc[6], p3.x, wp); fma2(acc[7], p3.y, wp);
                }
                ulonglong2* dst = (ulonglong2*)&pre[xp][j][bbase];
                dst[0] = make_ulonglong2(acc[0], acc[1]);
                dst[1] = make_ulonglong2(acc[2], acc[3]);
                dst[2] = make_ulonglong2(acc[4], acc[5]);
                dst[3] = make_ulonglong2(acc[6], acc[7]);
            }
        } else if (isIO) {
            if (t < 510) {
                if (layer > 0 && tid == 224) spinwait(inflag, t + 3);
                __syncwarp();
                int lane = tid - 224;
                const float* src = in + (size_t)(t + 2) * 3200 + b0;
                #pragma unroll
                for (int k = 0; k < 25; k++) xbuf[par][k][lane] = src[k * 128 + lane];
            }
        }
        __syncthreads();

        // phase B: state update + publish h
        if (isRec) {
            float4 gi = *(const float4*)&pre[par][u     ][bb];
            float4 gf = *(const float4*)&pre[par][u + 25][bb];
            float4 gg = *(const float4*)&pre[par][u + 50][bb];
            float4 go = *(const float4*)&pre[par][u + 75][bb];
            cst.x = gf.x * cst.x + gi.x * gg.x;
            cst.y = gf.y * cst.y + gi.y * gg.y;
            cst.z = gf.z * cst.z + gi.z * gg.z;
            cst.w = gf.w * cst.w + gi.w * gg.w;
            float4 h4 = make_float4(go.x * ftanh(cst.x), go.y * ftanh(cst.y),
                                    go.z * ftanh(cst.z), go.w * ftanh(cst.w));
            *(float4*)&hbuf[u][bb] = h4;
            *(float4*)(outp + (size_t)t * 3200 + u * 128 + b0 + bb) = h4;
        }
        __syncthreads();
        if (tid == 0) {
            int nv = t + 1;
            asm volatile("st.release.gpu.global.b32 [%0], %1;" :: "l"(outflag), "r"(nv) : "memory");
        }
    }
}

// ---------------- launcher ---------------------------------------------------
extern "C" void kernel_launch(void* const* d_in, const int* in_sizes, int n_in,
                              void* d_out, int out_size)
{
    const float* x     = (const float*)d_in[0];
    const float* cross = (const float*)d_in[1];
    const float* Wq_s = (const float*)d_in[2];  const float* bq_s = (const float*)d_in[3];
    const float* Wk_s = (const float*)d_in[4];  const float* bk_s = (const float*)d_in[5];
    const float* Wv_s = (const float*)d_in[6];  const float* bv_s = (const float*)d_in[7];
    const float* Wo_s = (const float*)d_in[8];  const float* bo_s = (const float*)d_in[9];
    const float* Wq_c = (const float*)d_in[10]; const float* bq_c = (const float*)d_in[11];
    const float* Wk_c = (const float*)d_in[12]; const float* bk_c = (const float*)d_in[13];
    const float* Wv_c = (const float*)d_in[14]; const float* bv_c = (const float*)d_in[15];
    const float* Wo_c = (const float*)d_in[16]; const float* bo_c = (const float*)d_in[17];
    const float* g1 = (const float*)d_in[18]; const float* b1 = (const float*)d_in[19];
    const float* g2 = (const float*)d_in[20]; const float* b2 = (const float*)d_in[21];
    const float* g3 = (const float*)d_in[22]; const float* b3 = (const float*)d_in[23];
    const float* W_ih = (const float*)d_in[24];
    const float* W_hh = (const float*)d_in[25];
    const float* b_ih = (const float*)d_in[26];
    const float* b_hh = (const float*)d_in[27];
    const float* Wc = (const float*)d_in[28]; const float* bc = (const float*)d_in[29];
    float* out = (float*)d_out;

    float *gq, *gk, *gv, *gctx, *gx1, *gx2, *gtmp, *gyt, *gY;
    cudaGetSymbolAddress((void**)&gq,   g_q);
    cudaGetSymbolAddress((void**)&gk,   g_k);
    cudaGetSymbolAddress((void**)&gv,   g_v);
    cudaGetSymbolAddress((void**)&gctx, g_ctx);
    cudaGetSymbolAddress((void**)&gx1,  g_x1);
    cudaGetSymbolAddress((void**)&gx2,  g_x2);
    cudaGetSymbolAddress((void**)&gtmp, g_tmp);
    cudaGetSymbolAddress((void**)&gyt,  g_yt);
    cudaGetSymbolAddress((void**)&gY,   g_Y);

    const int M1 = 3200;    // B*L
    zero_flags_kernel<<<17, 256>>>();

    // ---- self attention ----
    {
        GemmSet s = {{Wq_s, Wk_s, Wv_s}, {bq_s, bk_s, bv_s},
                     {nullptr, nullptr, nullptr}, {gq, gk, gv}};
        gemm_db_kernel<false><<<dim3(50, 8, 3), 128>>>(x, s);
    }
    attn_kernel<<<128 * 8, 256>>>(gq, gk, gv, gctx, 25);
    {
        GemmSet s = {{Wo_s, nullptr, nullptr}, {bo_s, nullptr, nullptr},
                     {x, nullptr, nullptr}, {gtmp, nullptr, nullptr}};
        gemm_db_kernel<false><<<dim3(50, 8, 1), 128>>>(gctx, s);
    }
    ln_kernel<<<M1 / 8, 256>>>(gtmp, g1, b1, gx1, M1);

    // ---- cross attention ----
    {
        GemmSet s = {{Wq_c, nullptr, nullptr}, {bq_c, nullptr, nullptr},
                     {nullptr, nullptr, nullptr}, {gq, nullptr, nullptr}};
        gemm_db_kernel<false><<<dim3(50, 8, 1), 128>>>(gx1, s);
    }
    {
        GemmSet s = {{Wk_c, Wv_c, nullptr}, {bk_c, bv_c, nullptr},
                     {nullptr, nullptr, nullptr}, {gk, gv, nullptr}};
        gemm_db_kernel<false><<<dim3(192, 8, 2), 128>>>(cross, s);
    }
    attn_kernel<<<128 * 8, 256>>>(gq, gk, gv, gctx, 96);
    {
        GemmSet s = {{Wo_c, nullptr, nullptr}, {bo_c, nullptr, nullptr},
                     {gx1, nullptr, nullptr}, {gtmp, nullptr, nullptr}};
        gemm_db_kernel<false><<<dim3(50, 8, 1), 128>>>(gctx, s);
    }
    ln_kernel<<<M1 / 8, 256>>>(gtmp, g2, b2, gx2, M1);

    // ---- LSTM wavefront over feature axis ----
    transpose_in_kernel<<<dim3(16, 4, 25), dim3(32, 8)>>>(gx2, gY);
    lstm_wave_kernel<<<128, 512>>>(W_ih, W_hh, b_ih, b_hh);

    // ---- pointwise conv + residual + final LN ----
    transpose_out_kernel<<<dim3(16, 4, 25), dim3(32, 8)>>>(gY + 32ull * YSTRIDE, gyt);
    {
        GemmSet s = {{Wc, nullptr, nullptr}, {bc, nullptr, nullptr},
                     {gx2, nullptr, nullptr}, {gtmp, nullptr, nullptr}};
        gemm_db_kernel<true><<<dim3(50, 8, 1), 128>>>(gyt, s);
    }
    ln_kernel<<<M1 / 8, 256>>>(gtmp, g3, b3, out, M1);
}

// round 6
// speedup vs baseline: 1.7569x; 1.7569x over previous
#include <cuda_runtime.h>
#include <cstddef>

#define DEVF __device__ __forceinline__
typedef unsigned long long ull;

// ---------------- scratch (device globals; no allocations allowed) ----------
__device__ float g_q  [3200 * 512];
__device__ float g_k  [12288 * 512];
__device__ float g_v  [12288 * 512];
__device__ float g_ctx[3200 * 512];
__device__ float g_x1 [3200 * 512];
__device__ float g_x2 [3200 * 512];
__device__ float g_tmp[3200 * 512];
__device__ float g_yt [3200 * 512];

// LSTM wavefront buffers: Y[l][t][k][b], l = 0..32, t<512, k<25, b<128
#define YSTRIDE 1638400   // 512*25*128
__device__ float g_Y[33ull * YSTRIDE];
__device__ int   g_flags[33 * 4 * 32];   // (layer,chunk) progress, 128B padded

// ---------------- f32x2 packed helpers ---------------------------------------
DEVF void fma2(ull& d, ull a, ull b) {
    asm("fma.rn.f32x2 %0, %1, %2, %0;" : "+l"(d) : "l"(a), "l"(b));
}
DEVF ull splat2(float x) {
    ull r; unsigned ix = __float_as_uint(x);
    asm("mov.b64 %0, {%1, %1};" : "=l"(r) : "r"(ix));
    return r;
}
DEVF float2 unpack2(ull v) {
    unsigned lo, hi;
    asm("mov.b64 {%0, %1}, %2;" : "=r"(lo), "=r"(hi) : "l"(v));
    return make_float2(__uint_as_float(lo), __uint_as_float(hi));
}

// ---------------- activations ------------------------------------------------
DEVF float fsig(float x) { return 1.f / (1.f + __expf(-x)); }
DEVF float tanh_fast(float x) {
    float y; asm("tanh.approx.f32 %0, %1;" : "=f"(y) : "f"(x)); return y;
}
DEVF float sig_fast(float x) { return fmaf(tanh_fast(0.5f * x), 0.5f, 0.5f); }

// ---------------- GEMM: 64x64 tile, 128 threads, double-buffered, f32x2 ------
// C[.,512] = A[.,512] @ W (+bias)(+res). TRANSW: W stored [N,K] else [K,N].
template<bool TRANSW>
DEVF void gemm_core(const float* __restrict__ A, const float* __restrict__ W,
                    const float* __restrict__ bias, const float* __restrict__ res,
                    float* __restrict__ C)
{
    __shared__ __align__(16) float As[2][16][64];
    __shared__ __align__(16) float Bs[2][16][64];
    int tid = threadIdx.x;
    int bm = blockIdx.x * 64, bn = blockIdx.y * 64;
    int tx = tid & 15, ty = tid >> 4;

    ull acc[4][4];
    #pragma unroll
    for (int i = 0; i < 4; i++)
        #pragma unroll
        for (int j = 0; j < 4; j++) acc[i][j] = 0ull;

    int ar = tid >> 1;           // 0..63
    int ac = (tid & 1) * 8;      // 0 or 8
    const float* Arow = A + (size_t)(bm + ar) * 512 + ac;

    int b_kk = tid >> 3, b_nn = (tid & 7) * 8;    // !TRANSW
    int b_n2 = tid >> 1, b_k2 = (tid & 1) * 8;    // TRANSW

    float4 a0, a1, bv0, bv1;
    a0 = *(const float4*)(Arow + 0);
    a1 = *(const float4*)(Arow + 4);
    if (!TRANSW) {
        bv0 = *(const float4*)(W + (size_t)b_kk * 512 + bn + b_nn);
        bv1 = *(const float4*)(W + (size_t)b_kk * 512 + bn + b_nn + 4);
    } else {
        bv0 = *(const float4*)(W + (size_t)(bn + b_n2) * 512 + b_k2);
        bv1 = *(const float4*)(W + (size_t)(bn + b_n2) * 512 + b_k2 + 4);
    }
    As[0][ac + 0][ar] = a0.x; As[0][ac + 1][ar] = a0.y;
    As[0][ac + 2][ar] = a0.z; As[0][ac + 3][ar] = a0.w;
    As[0][ac + 4][ar] = a1.x; As[0][ac + 5][ar] = a1.y;
    As[0][ac + 6][ar] = a1.z; As[0][ac + 7][ar] = a1.w;
    if (!TRANSW) {
        *(float4*)&Bs[0][b_kk][b_nn]     = bv0;
        *(float4*)&Bs[0][b_kk][b_nn + 4] = bv1;
    } else {
        Bs[0][b_k2 + 0][b_n2] = bv0.x; Bs[0][b_k2 + 1][b_n2] = bv0.y;
        Bs[0][b_k2 + 2][b_n2] = bv0.z; Bs[0][b_k2 + 3][b_n2] = bv0.w;
        Bs[0][b_k2 + 4][b_n2] = bv1.x; Bs[0][b_k2 + 5][b_n2] = bv1.y;
        Bs[0][b_k2 + 6][b_n2] = bv1.z; Bs[0][b_k2 + 7][b_n2] = bv1.w;
    }
    __syncthreads();

    for (int it = 0; it < 32; it++) {
        int buf = it & 1;
        if (it < 31) {
            int k0 = (it + 1) * 16;
            a0 = *(const float4*)(Arow + k0);
            a1 = *(const float4*)(Arow + k0 + 4);
            if (!TRANSW) {
                bv0 = *(const float4*)(W + (size_t)(k0 + b_kk) * 512 + bn + b_nn);
                bv1 = *(const float4*)(W + (size_t)(k0 + b_kk) * 512 + bn + b_nn + 4);
            } else {
                bv0 = *(const float4*)(W + (size_t)(bn + b_n2) * 512 + k0 + b_k2);
                bv1 = *(const float4*)(W + (size_t)(bn + b_n2) * 512 + k0 + b_k2 + 4);
            }
        }
        #pragma unroll
        for (int k = 0; k < 16; k++) {
            ulonglong2 a01 = *(const ulonglong2*)&As[buf][k][ty * 8];
            ulonglong2 a23 = *(const ulonglong2*)&As[buf][k][ty * 8 + 4];
            float4 b4 = *(const float4*)&Bs[buf][k][tx * 4];
            ull bs0 = splat2(b4.x), bs1 = splat2(b4.y);
            ull bs2 = splat2(b4.z), bs3 = splat2(b4.w);
            fma2(acc[0][0], a01.x, bs0); fma2(acc[0][1], a01.x, bs1);
            fma2(acc[0][2], a01.x, bs2); fma2(acc[0][3], a01.x, bs3);
            fma2(acc[1][0], a01.y, bs0); fma2(acc[1][1], a01.y, bs1);
            fma2(acc[1][2], a01.y, bs2); fma2(acc[1][3], a01.y, bs3);
            fma2(acc[2][0], a23.x, bs0); fma2(acc[2][1], a23.x, bs1);
            fma2(acc[2][2], a23.x, bs2); fma2(acc[2][3], a23.x, bs3);
            fma2(acc[3][0], a23.y, bs0); fma2(acc[3][1], a23.y, bs1);
            fma2(acc[3][2], a23.y, bs2); fma2(acc[3][3], a23.y, bs3);
        }
        if (it < 31) {
            int nb = buf ^ 1;
            As[nb][ac + 0][ar] = a0.x; As[nb][ac + 1][ar] = a0.y;
            As[nb][ac + 2][ar] = a0.z; As[nb][ac + 3][ar] = a0.w;
            As[nb][ac + 4][ar] = a1.x; As[nb][ac + 5][ar] = a1.y;
            As[nb][ac + 6][ar] = a1.z; As[nb][ac + 7][ar] = a1.w;
            if (!TRANSW) {
                *(float4*)&Bs[nb][b_kk][b_nn]     = bv0;
                *(float4*)&Bs[nb][b_kk][b_nn + 4] = bv1;
            } else {
                Bs[nb][b_k2 + 0][b_n2] = bv0.x; Bs[nb][b_k2 + 1][b_n2] = bv0.y;
                Bs[nb][b_k2 + 2][b_n2] = bv0.z; Bs[nb][b_k2 + 3][b_n2] = bv0.w;
                Bs[nb][b_k2 + 4][b_n2] = bv1.x; Bs[nb][b_k2 + 5][b_n2] = bv1.y;
                Bs[nb][b_k2 + 6][b_n2] = bv1.z; Bs[nb][b_k2 + 7][b_n2] = bv1.w;
            }
        }
        __syncthreads();
    }

    float4 bv4 = *(const float4*)(bias + bn + tx * 4);
    float bb[4] = {bv4.x, bv4.y, bv4.z, bv4.w};
    #pragma unroll
    for (int mp = 0; mp < 4; mp++) {
        int m = bm + ty * 8 + mp * 2;
        float r0[4], r1[4];
        #pragma unroll
        for (int n = 0; n < 4; n++) {
            float2 f = unpack2(acc[mp][n]);
            r0[n] = f.x + bb[n];
            r1[n] = f.y + bb[n];
        }
        if (res) {
            float4 q0 = *(const float4*)(res + (size_t)m * 512 + bn + tx * 4);
            float4 q1 = *(const float4*)(res + (size_t)(m + 1) * 512 + bn + tx * 4);
            r0[0] += q0.x; r0[1] += q0.y; r0[2] += q0.z; r0[3] += q0.w;
            r1[0] += q1.x; r1[1] += q1.y; r1[2] += q1.z; r1[3] += q1.w;
        }
        *(float4*)(C + (size_t)m * 512 + bn + tx * 4) = make_float4(r0[0], r0[1], r0[2], r0[3]);
        *(float4*)(C + (size_t)(m + 1) * 512 + bn + tx * 4) = make_float4(r1[0], r1[1], r1[2], r1[3]);
    }
}

struct GemmSet {
    const float* W[3];
    const float* b[3];
    const float* r[3];
    float*       C[3];
};

template<bool TRANSW>
__global__ void __launch_bounds__(128, 5) gemm_db_kernel(const float* __restrict__ A, GemmSet s) {
    int z = blockIdx.z;
    gemm_core<TRANSW>(A, s.W[z], s.b[z], s.r[z], s.C[z]);
}

// ---------------- attention core: one block per (b, h), 256 threads ---------
__global__ void __launch_bounds__(256) attn_kernel(
    const float* __restrict__ Q, const float* __restrict__ Kp,
    const float* __restrict__ Vp, float* __restrict__ O, int S)
{
    __shared__ float qs[25 * 64];
    __shared__ float kv[96 * 64];
    __shared__ float sc[25 * 96];
    int b = blockIdx.x >> 3, h = blockIdx.x & 7;
    int tid = threadIdx.x;
    const float scale = 0.125f;
    size_t qbase = (size_t)b * 25 * 512 + h * 64;
    size_t kbase = (size_t)b * S  * 512 + h * 64;

    for (int i = tid; i < 25 * 64; i += 256) qs[i] = Q[qbase + (size_t)(i >> 6) * 512 + (i & 63)];
    for (int i = tid; i < S  * 64; i += 256) kv[i] = Kp[kbase + (size_t)(i >> 6) * 512 + (i & 63)];
    __syncthreads();

    for (int i = tid; i < 25 * S; i += 256) {
        int l = i / S, s = i - l * S;
        float acc = 0.f;
        #pragma unroll 16
        for (int e = 0; e < 64; e++) acc += qs[l * 64 + e] * kv[s * 64 + e];
        sc[i] = acc * scale;
    }
    __syncthreads();

    int warp = tid >> 5, lane = tid & 31;
    for (int l = warp; l < 25; l += 8) {
        float mx = -1e30f;
        for (int s = lane; s < S; s += 32) mx = fmaxf(mx, sc[l * S + s]);
        #pragma unroll
        for (int o = 16; o; o >>= 1) mx = fmaxf(mx, __shfl_xor_sync(~0u, mx, o));
        float sum = 0.f;
        for (int s = lane; s < S; s += 32) {
            float e = __expf(sc[l * S + s] - mx);
            sc[l * S + s] = e; sum += e;
        }
        #pragma unroll
        for (int o = 16; o; o >>= 1) sum += __shfl_xor_sync(~0u, sum, o);
        float inv = __fdividef(1.f, sum);
        for (int s = lane; s < S; s += 32) sc[l * S + s] *= inv;
    }
    __syncthreads();

    for (int i = tid; i < S * 64; i += 256) kv[i] = Vp[kbase + (size_t)(i >> 6) * 512 + (i & 63)];
    __syncthreads();

    for (int i = tid; i < 25 * 64; i += 256) {
        int l = i >> 6, e = i & 63;
        float acc = 0.f;
        for (int s = 0; s < S; s++) acc += sc[l * S + s] * kv[s * 64 + e];
        O[qbase + (size_t)l * 512 + e] = acc;
    }
}

// ---------------- LayerNorm over rows of 512 (warp per row) ------------------
__global__ void __launch_bounds__(256) ln_kernel(
    const float* __restrict__ in, const float* __restrict__ g,
    const float* __restrict__ bb, float* __restrict__ out, int M)
{
    int row = blockIdx.x * 8 + (threadIdx.x >> 5);
    int lane = threadIdx.x & 31;
    if (row >= M) return;
    const float* p = in + (size_t)row * 512;
    float v[16];
    float s = 0.f, s2 = 0.f;
    #pragma unroll
    for (int i = 0; i < 16; i++) {
        v[i] = p[lane + 32 * i];
        s += v[i]; s2 += v[i] * v[i];
    }
    #pragma unroll
    for (int o = 16; o; o >>= 1) {
        s  += __shfl_xor_sync(~0u, s,  o);
        s2 += __shfl_xor_sync(~0u, s2, o);
    }
    float mean = s * (1.f / 512.f);
    float var  = s2 * (1.f / 512.f) - mean * mean;
    float rstd = rsqrtf(var + 1e-5f);
    float* q = out + (size_t)row * 512;
    #pragma unroll
    for (int i = 0; i < 16; i++) {
        int d = lane + 32 * i;
        q[d] = (v[i] - mean) * rstd * g[d] + bb[d];
    }
}

// ---------------- tiled transposes -------------------------------------------
__global__ void transpose_in_kernel(const float* __restrict__ in, float* __restrict__ out) {
    __shared__ float tile[32][33];
    int tx = threadIdx.x, ty = threadIdx.y;
    int t0 = blockIdx.x * 32, b0 = blockIdx.y * 32, k = blockIdx.z;
    #pragma unroll
    for (int i = 0; i < 4; i++)
        tile[ty + 8 * i][tx] = in[(size_t)(b0 + ty + 8 * i) * 12800 + k * 512 + t0 + tx];
    __syncthreads();
    #pragma unroll
    for (int i = 0; i < 4; i++)
        out[(size_t)(t0 + ty + 8 * i) * 3200 + k * 128 + b0 + tx] = tile[tx][ty + 8 * i];
}
__global__ void transpose_out_kernel(const float* __restrict__ in, float* __restrict__ out) {
    __shared__ float tile[32][33];
    int tx = threadIdx.x, ty = threadIdx.y;
    int c0 = blockIdx.x * 32, b0 = blockIdx.y * 32, l = blockIdx.z;
    #pragma unroll
    for (int i = 0; i < 4; i++)
        tile[ty + 8 * i][tx] = in[(size_t)(c0 + ty + 8 * i) * 3200 + l * 128 + b0 + tx];
    __syncthreads();
    #pragma unroll
    for (int i = 0; i < 4; i++)
        out[(size_t)((b0 + ty + 8 * i) * 25 + l) * 512 + c0 + tx] = tile[tx][ty + 8 * i];
}

__global__ void zero_flags_kernel() {
    int i = blockIdx.x * 256 + threadIdx.x;
    if (i < 33 * 4 * 32) g_flags[i] = 0;
}

DEVF void spinwait(const int* p, int need) {
    int v;
    do {
        asm volatile("ld.acquire.gpu.global.b32 %0, [%1];" : "=r"(v) : "l"(p) : "memory");
    } while (v < need);
}

// ---------------- LSTM wavefront: 128 blocks = 32 layers x 4 chunks ----------
// 256 threads. Warps 0-6 (tid<200): gate compute + state update. Warp 7: IO
// (flag wait + x prefetch). tanh.approx activations; weights pre-splatted;
// gates stride 36 (bank-conflict pad). 2 barriers/step.
#define GSTR 36
__global__ void __launch_bounds__(256, 1) lstm_wave_kernel(
    const float* __restrict__ Wih, const float* __restrict__ Whh,
    const float* __restrict__ bih, const float* __restrict__ bhh)
{
    int layer = blockIdx.x & 31;
    int chunk = blockIdx.x >> 5;
    int b0 = chunk * 32;
    const float* in  = g_Y + (size_t)layer * YSTRIDE;
    float* outp      = g_Y + (size_t)(layer + 1) * YSTRIDE;
    const int* inflag = g_flags + (layer * 4 + chunk) * 32;
    int* outflag      = g_flags + ((layer + 1) * 4 + chunk) * 32;

    __shared__ __align__(16) float xbuf[2][25][32];
    __shared__ __align__(16) float hbuf[25][32];
    __shared__ __align__(16) float gates[100][GSTR];

    int tid = threadIdx.x;
    int warp = tid >> 5;

    // gate role
    int j = tid >> 1, bbase = (tid & 1) << 4;
    ull wsp[50];
    ull bias2 = 0ull;
    if (tid < 200) {
        const float* wi = Wih + (size_t)layer * 2500 + j * 25;
        const float* wh = Whh + (size_t)layer * 2500 + j * 25;
        #pragma unroll
        for (int k = 0; k < 25; k++) { wsp[k] = splat2(wi[k]); wsp[25 + k] = splat2(wh[k]); }
        bias2 = splat2(bih[layer * 100 + j] + bhh[layer * 100 + j]);
    }
    bool isg = (j >= 50 && j < 75);
    // update role
    int u = tid >> 3, bb = (tid & 7) << 2;
    float4 cst = make_float4(0.f, 0.f, 0.f, 0.f);

    for (int i = tid; i < 800; i += 256) hbuf[i >> 5][i & 31] = 0.f;

    // prologue: load x_0
    if (warp == 7) {
        if (layer > 0 && tid == 224) spinwait(inflag, 1);
        __syncwarp();
        int lane = tid - 224;
        #pragma unroll
        for (int k = 0; k < 25; k++) xbuf[0][k][lane] = in[k * 128 + b0 + lane];
    }
    __syncthreads();

    for (int t = 0; t < 512; t++) {
        int par = t & 1;
        // phase A: gates (warps 0-6) || prefetch x_{t+1} + flag wait (warp 7)
        if (tid < 200) {
            ull acc[8];
            #pragma unroll
            for (int q = 0; q < 8; q++) acc[q] = bias2;
            #pragma unroll
            for (int k = 0; k < 25; k++) {
                ull wp = wsp[k];
                const ulonglong2* row = (const ulonglong2*)&xbuf[par][k][bbase];
                ulonglong2 p0 = row[0], p1 = row[1], p2 = row[2], p3 = row[3];
                fma2(acc[0], p0.x, wp); fma2(acc[1], p0.y, wp);
                fma2(acc[2], p1.x, wp); fma2(acc[3], p1.y, wp);
                fma2(acc[4], p2.x, wp); fma2(acc[5], p2.y, wp);
                fma2(acc[6], p3.x, wp); fma2(acc[7], p3.y, wp);
            }
            #pragma unroll
            for (int k = 0; k < 25; k++) {
                ull wp = wsp[25 + k];
                const ulonglong2* row = (const ulonglong2*)&hbuf[k][bbase];
                ulonglong2 p0 = row[0], p1 = row[1], p2 = row[2], p3 = row[3];
                fma2(acc[0], p0.x, wp); fma2(acc[1], p0.y, wp);
                fma2(acc[2], p1.x, wp); fma2(acc[3], p1.y, wp);
                fma2(acc[4], p2.x, wp); fma2(acc[5], p2.y, wp);
                fma2(acc[6], p3.x, wp); fma2(acc[7], p3.y, wp);
            }
            float g16[16];
            #pragma unroll
            for (int q = 0; q < 8; q++) {
                float2 f = unpack2(acc[q]);
                g16[2 * q] = f.x; g16[2 * q + 1] = f.y;
            }
            #pragma unroll
            for (int i = 0; i < 16; i++) g16[i] = isg ? tanh_fast(g16[i]) : sig_fast(g16[i]);
            float4* gp = (float4*)&gates[j][bbase];
            gp[0] = make_float4(g16[0],  g16[1],  g16[2],  g16[3]);
            gp[1] = make_float4(g16[4],  g16[5],  g16[6],  g16[7]);
            gp[2] = make_float4(g16[8],  g16[9],  g16[10], g16[11]);
            gp[3] = make_float4(g16[12], g16[13], g16[14], g16[15]);
        } else if (warp == 7) {
            if (t < 511) {
                if (layer > 0 && tid == 224) spinwait(inflag, t + 2);
                __syncwarp();
                int lane = tid - 224;
                const float* src = in + (size_t)(t + 1) * 3200 + b0;
                #pragma unroll
                for (int k = 0; k < 25; k++) xbuf[par ^ 1][k][lane] = src[k * 128 + lane];
            }
        }
        __syncthreads();

        // phase B: state update + publish h
        if (tid < 200) {
            float4 gi = *(const float4*)&gates[u     ][bb];
            float4 gf = *(const float4*)&gates[u + 25][bb];
            float4 gg = *(const float4*)&gates[u + 50][bb];
            float4 go = *(const float4*)&gates[u + 75][bb];
            cst.x = gf.x * cst.x + gi.x * gg.x;
            cst.y = gf.y * cst.y + gi.y * gg.y;
            cst.z = gf.z * cst.z + gi.z * gg.z;
            cst.w = gf.w * cst.w + gi.w * gg.w;
            float4 h4 = make_float4(go.x * tanh_fast(cst.x), go.y * tanh_fast(cst.y),
                                    go.z * tanh_fast(cst.z), go.w * tanh_fast(cst.w));
            *(float4*)&hbuf[u][bb] = h4;
            *(float4*)(outp + (size_t)t * 3200 + u * 128 + b0 + bb) = h4;
        }
        __syncthreads();
        if (tid == 0) {
            int nv = t + 1;
            asm volatile("st.release.gpu.global.b32 [%0], %1;" :: "l"(outflag), "r"(nv) : "memory");
        }
    }
}

// ---------------- launcher ---------------------------------------------------
extern "C" void kernel_launch(void* const* d_in, const int* in_sizes, int n_in,
                              void* d_out, int out_size)
{
    const float* x     = (const float*)d_in[0];
    const float* cross = (const float*)d_in[1];
    const float* Wq_s = (const float*)d_in[2];  const float* bq_s = (const float*)d_in[3];
    const float* Wk_s = (const float*)d_in[4];  const float* bk_s = (const float*)d_in[5];
    const float* Wv_s = (const float*)d_in[6];  const float* bv_s = (const float*)d_in[7];
    const float* Wo_s = (const float*)d_in[8];  const float* bo_s = (const float*)d_in[9];
    const float* Wq_c = (const float*)d_in[10]; const float* bq_c = (const float*)d_in[11];
    const float* Wk_c = (const float*)d_in[12]; const float* bk_c = (const float*)d_in[13];
    const float* Wv_c = (const float*)d_in[14]; const float* bv_c = (const float*)d_in[15];
    const float* Wo_c = (const float*)d_in[16]; const float* bo_c = (const float*)d_in[17];
    const float* g1 = (const float*)d_in[18]; const float* b1 = (const float*)d_in[19];
    const float* g2 = (const float*)d_in[20]; const float* b2 = (const float*)d_in[21];
    const float* g3 = (const float*)d_in[22]; const float* b3 = (const float*)d_in[23];
    const float* W_ih = (const float*)d_in[24];
    const float* W_hh = (const float*)d_in[25];
    const float* b_ih = (const float*)d_in[26];
    const float* b_hh = (const float*)d_in[27];
    const float* Wc = (const float*)d_in[28]; const float* bc = (const float*)d_in[29];
    float* out = (float*)d_out;

    float *gq, *gk, *gv, *gctx, *gx1, *gx2, *gtmp, *gyt, *gY;
    cudaGetSymbolAddress((void**)&gq,   g_q);
    cudaGetSymbolAddress((void**)&gk,   g_k);
    cudaGetSymbolAddress((void**)&gv,   g_v);
    cudaGetSymbolAddress((void**)&gctx, g_ctx);
    cudaGetSymbolAddress((void**)&gx1,  g_x1);
    cudaGetSymbolAddress((void**)&gx2,  g_x2);
    cudaGetSymbolAddress((void**)&gtmp, g_tmp);
    cudaGetSymbolAddress((void**)&gyt,  g_yt);
    cudaGetSymbolAddress((void**)&gY,   g_Y);

    const int M1 = 3200;    // B*L
    zero_flags_kernel<<<17, 256>>>();

    // ---- self attention ----
    {
        GemmSet s = {{Wq_s, Wk_s, Wv_s}, {bq_s, bk_s, bv_s},
                     {nullptr, nullptr, nullptr}, {gq, gk, gv}};
        gemm_db_kernel<false><<<dim3(50, 8, 3), 128>>>(x, s);
    }
    attn_kernel<<<128 * 8, 256>>>(gq, gk, gv, gctx, 25);
    {
        GemmSet s = {{Wo_s, nullptr, nullptr}, {bo_s, nullptr, nullptr},
                     {x, nullptr, nullptr}, {gtmp, nullptr, nullptr}};
        gemm_db_kernel<false><<<dim3(50, 8, 1), 128>>>(gctx, s);
    }
    ln_kernel<<<M1 / 8, 256>>>(gtmp, g1, b1, gx1, M1);

    // ---- cross attention ----
    {
        GemmSet s = {{Wq_c, nullptr, nullptr}, {bq_c, nullptr, nullptr},
                     {nullptr, nullptr, nullptr}, {gq, nullptr, nullptr}};
        gemm_db_kernel<false><<<dim3(50, 8, 1), 128>>>(gx1, s);
    }
    {
        GemmSet s = {{Wk_c, Wv_c, nullptr}, {bk_c, bv_c, nullptr},
                     {nullptr, nullptr, nullptr}, {gk, gv, nullptr}};
        gemm_db_kernel<false><<<dim3(192, 8, 2), 128>>>(cross, s);
    }
    attn_kernel<<<128 * 8, 256>>>(gq, gk, gv, gctx, 96);
    {
        GemmSet s = {{Wo_c, nullptr, nullptr}, {bo_c, nullptr, nullptr},
                     {gx1, nullptr, nullptr}, {gtmp, nullptr, nullptr}};
        gemm_db_kernel<false><<<dim3(50, 8, 1), 128>>>(gctx, s);
    }
    ln_kernel<<<M1 / 8, 256>>>(gtmp, g2, b2, gx2, M1);

    // ---- LSTM wavefront over feature axis ----
    transpose_in_kernel<<<dim3(16, 4, 25), dim3(32, 8)>>>(gx2, gY);
    lstm_wave_kernel<<<128, 256>>>(W_ih, W_hh, b_ih, b_hh);

    // ---- pointwise conv + residual + final LN ----
    transpose_out_kernel<<<dim3(16, 4, 25), dim3(32, 8)>>>(gY + 32ull * YSTRIDE, gyt);
    {
        GemmSet s = {{Wc, nullptr, nullptr}, {bc, nullptr, nullptr},
                     {gx2, nullptr, nullptr}, {gtmp, nullptr, nullptr}};
        gemm_db_kernel<true><<<dim3(50, 8, 1), 128>>>(gyt, s);
    }
    ln_kernel<<<M1 / 8, 256>>>(gtmp, g3, b3, out, M1);
}

// round 7
// speedup vs baseline: 1.9922x; 1.1340x over previous
#include <cuda_runtime.h>
#include <cstddef>

#define DEVF __device__ __forceinline__
typedef unsigned long long ull;

// ---------------- scratch (device globals; no allocations allowed) ----------
__device__ float g_q  [3200 * 512];
__device__ float g_k  [12288 * 512];
__device__ float g_v  [12288 * 512];
__device__ float g_ctx[3200 * 512];
__device__ float g_x1 [3200 * 512];
__device__ float g_x2 [3200 * 512];
__device__ float g_tmp[3200 * 512];
__device__ float g_yt [3200 * 512];

// LSTM wavefront buffers: Y[l][t][k][b], l = 0..32, t<512, k<25, b<128
#define YSTRIDE 1638400   // 512*25*128
__device__ float g_Y[33ull * YSTRIDE];
__device__ int   g_flags[33 * 4 * 32];   // (layer,chunk) progress, 128B padded

// ---------------- f32x2 packed helpers (LSTM) --------------------------------
DEVF void fma2(ull& d, ull a, ull b) {
    asm("fma.rn.f32x2 %0, %1, %2, %0;" : "+l"(d) : "l"(a), "l"(b));
}
DEVF ull splat2(float x) {
    ull r; unsigned ix = __float_as_uint(x);
    asm("mov.b64 %0, {%1, %1};" : "=l"(r) : "r"(ix));
    return r;
}
DEVF float2 unpack2(ull v) {
    unsigned lo, hi;
    asm("mov.b64 {%0, %1}, %2;" : "=r"(lo), "=r"(hi) : "l"(v));
    return make_float2(__uint_as_float(lo), __uint_as_float(hi));
}

// ---------------- activations ------------------------------------------------
DEVF float tanh_fast(float x) {
    float y; asm("tanh.approx.f32 %0, %1;" : "=f"(y) : "f"(x)); return y;
}
DEVF float sig_fast(float x) { return fmaf(tanh_fast(0.5f * x), 0.5f, 0.5f); }

// ---------------- tf32 helpers -----------------------------------------------
DEVF unsigned totf(float x) {
    unsigned r; asm("cvt.rna.tf32.f32 %0, %1;" : "=r"(r) : "f"(x)); return r;
}
DEVF uint4 totf4(float4 v) { return make_uint4(totf(v.x), totf(v.y), totf(v.z), totf(v.w)); }

DEVF void mma_tf32(float* c, const unsigned* a, unsigned b0, unsigned b1) {
    asm("mma.sync.aligned.m16n8k8.row.col.f32.tf32.tf32.f32 "
        "{%0,%1,%2,%3}, {%4,%5,%6,%7}, {%8,%9}, {%0,%1,%2,%3};"
        : "+f"(c[0]), "+f"(c[1]), "+f"(c[2]), "+f"(c[3])
        : "r"(a[0]), "r"(a[1]), "r"(a[2]), "r"(a[3]), "r"(b0), "r"(b1));
}

// ---------------- tf32 tensor-core GEMM --------------------------------------
// C[.,512] = A[.,512] @ W (+bias)(+res). TRANSW: W stored [N,K] else [K,N].
// Tile 64x64xBK32, 128 threads = 2x2 warps, each warp 32x32.
template<bool TRANSW>
DEVF void gemm_tc_core(const float* __restrict__ A, const float* __restrict__ W,
                       const float* __restrict__ bias, const float* __restrict__ res,
                       float* __restrict__ C)
{
    __shared__ __align__(16) unsigned As[2][64][36];   // [m][k], stride 36: frag reads conflict-free
    __shared__ __align__(16) unsigned Bs[2][32][72];   // [k][n], stride 72: frag reads conflict-free

    int tid = threadIdx.x;
    int bm = blockIdx.x * 64, bn = blockIdx.y * 64;
    int lane = tid & 31, wid = tid >> 5;
    int wm = wid & 1, wn = wid >> 1;           // warp tile (32x32)
    int g = lane >> 2, tg = lane & 3;

    float acc[2][4][4];
    #pragma unroll
    for (int i = 0; i < 2; i++)
        #pragma unroll
        for (int j = 0; j < 4; j++)
            #pragma unroll
            for (int q = 0; q < 4; q++) acc[i][j][q] = 0.f;

    // A staging: thread row ar (0..63), half ac (0 or 16)
    int ar = tid >> 1, ac = (tid & 1) * 16;
    const float* Arow = A + (size_t)(bm + ar) * 512 + ac;
    // B staging (!TRANSW): row kk (0..31), quarter nn
    int kk = tid >> 2, nn = (tid & 3) * 16;
    // B staging (TRANSW): row nr (0..63), half kc
    int nr = tid >> 1, kc = (tid & 1) * 16;

    float4 aT[4], bT[4];

    // ---- prologue: fetch + store k-tile 0 ----
    #pragma unroll
    for (int j = 0; j < 4; j++) aT[j] = *(const float4*)(Arow + 4 * j);
    if (!TRANSW) {
        #pragma unroll
        for (int j = 0; j < 4; j++) bT[j] = *(const float4*)(W + (size_t)kk * 512 + bn + nn + 4 * j);
    } else {
        #pragma unroll
        for (int j = 0; j < 4; j++) bT[j] = *(const float4*)(W + (size_t)(bn + nr) * 512 + kc + 4 * j);
    }
    #pragma unroll
    for (int j = 0; j < 4; j++) *(uint4*)&As[0][ar][ac + 4 * j] = totf4(aT[j]);
    if (!TRANSW) {
        #pragma unroll
        for (int j = 0; j < 4; j++) *(uint4*)&Bs[0][kk][nn + 4 * j] = totf4(bT[j]);
    } else {
        #pragma unroll
        for (int j = 0; j < 4; j++) {
            Bs[0][kc + 4 * j + 0][nr] = totf(bT[j].x);
            Bs[0][kc + 4 * j + 1][nr] = totf(bT[j].y);
            Bs[0][kc + 4 * j + 2][nr] = totf(bT[j].z);
            Bs[0][kc + 4 * j + 3][nr] = totf(bT[j].w);
        }
    }
    __syncthreads();

    int am0 = wm * 32 + g;          // frag row base (mf adds 16)
    int bn0 = wn * 32 + g;          // frag col base (nf adds 8)

    for (int it = 0; it < 16; it++) {
        int buf = it & 1;
        if (it < 15) {
            int k0 = (it + 1) * 32;
            #pragma unroll
            for (int j = 0; j < 4; j++) aT[j] = *(const float4*)(Arow + k0 + 4 * j);
            if (!TRANSW) {
                #pragma unroll
                for (int j = 0; j < 4; j++) bT[j] = *(const float4*)(W + (size_t)(k0 + kk) * 512 + bn + nn + 4 * j);
            } else {
                #pragma unroll
                for (int j = 0; j < 4; j++) bT[j] = *(const float4*)(W + (size_t)(bn + nr) * 512 + k0 + kc + 4 * j);
            }
        }

        #pragma unroll
        for (int ks = 0; ks < 4; ks++) {
            int klo = ks * 8 + tg;
            unsigned afr[2][4];
            #pragma unroll
            for (int mf = 0; mf < 2; mf++) {
                int m = am0 + mf * 16;
                afr[mf][0] = As[buf][m][klo];
                afr[mf][1] = As[buf][m + 8][klo];
                afr[mf][2] = As[buf][m][klo + 4];
                afr[mf][3] = As[buf][m + 8][klo + 4];
            }
            #pragma unroll
            for (int nf = 0; nf < 4; nf++) {
                unsigned b0 = Bs[buf][klo][bn0 + nf * 8];
                unsigned b1 = Bs[buf][klo + 4][bn0 + nf * 8];
                mma_tf32(acc[0][nf], afr[0], b0, b1);
                mma_tf32(acc[1][nf], afr[1], b0, b1);
            }
        }

        if (it < 15) {
            int nb = buf ^ 1;
            #pragma unroll
            for (int j = 0; j < 4; j++) *(uint4*)&As[nb][ar][ac + 4 * j] = totf4(aT[j]);
            if (!TRANSW) {
                #pragma unroll
                for (int j = 0; j < 4; j++) *(uint4*)&Bs[nb][kk][nn + 4 * j] = totf4(bT[j]);
            } else {
                #pragma unroll
                for (int j = 0; j < 4; j++) {
                    Bs[nb][kc + 4 * j + 0][nr] = totf(bT[j].x);
                    Bs[nb][kc + 4 * j + 1][nr] = totf(bT[j].y);
                    Bs[nb][kc + 4 * j + 2][nr] = totf(bT[j].z);
                    Bs[nb][kc + 4 * j + 3][nr] = totf(bT[j].w);
                }
            }
        }
        __syncthreads();
    }

    // ---- epilogue: bias (+res) + store (c frags: rows g/g+8, cols 2tg/2tg+1) ----
    #pragma unroll
    for (int nf = 0; nf < 4; nf++) {
        int col = bn + wn * 32 + nf * 8 + 2 * tg;
        float2 bv = *(const float2*)(bias + col);
        #pragma unroll
        for (int mf = 0; mf < 2; mf++) {
            int row = bm + wm * 32 + mf * 16 + g;
            float2 v0 = make_float2(acc[mf][nf][0] + bv.x, acc[mf][nf][1] + bv.y);
            float2 v1 = make_float2(acc[mf][nf][2] + bv.x, acc[mf][nf][3] + bv.y);
            if (res) {
                float2 r0 = *(const float2*)(res + (size_t)row * 512 + col);
                float2 r1 = *(const float2*)(res + (size_t)(row + 8) * 512 + col);
                v0.x += r0.x; v0.y += r0.y; v1.x += r1.x; v1.y += r1.y;
            }
            *(float2*)(C + (size_t)row * 512 + col) = v0;
            *(float2*)(C + (size_t)(row + 8) * 512 + col) = v1;
        }
    }
}

struct GemmSet {
    const float* W[3];
    const float* b[3];
    const float* r[3];
    float*       C[3];
};

template<bool TRANSW>
__global__ void __launch_bounds__(128, 4) gemm_tc_kernel(const float* __restrict__ A, GemmSet s) {
    int z = blockIdx.z;
    gemm_tc_core<TRANSW>(A, s.W[z], s.b[z], s.r[z], s.C[z]);
}

// ---------------- attention core: one block per (b, h), 256 threads ---------
__global__ void __launch_bounds__(256) attn_kernel(
    const float* __restrict__ Q, const float* __restrict__ Kp,
    const float* __restrict__ Vp, float* __restrict__ O, int S)
{
    __shared__ float qs[25 * 64];
    __shared__ float kv[96 * 64];
    __shared__ float sc[25 * 96];
    int b = blockIdx.x >> 3, h = blockIdx.x & 7;
    int tid = threadIdx.x;
    const float scale = 0.125f;
    size_t qbase = (size_t)b * 25 * 512 + h * 64;
    size_t kbase = (size_t)b * S  * 512 + h * 64;

    for (int i = tid; i < 25 * 64; i += 256) qs[i] = Q[qbase + (size_t)(i >> 6) * 512 + (i & 63)];
    for (int i = tid; i < S  * 64; i += 256) kv[i] = Kp[kbase + (size_t)(i >> 6) * 512 + (i & 63)];
    __syncthreads();

    for (int i = tid; i < 25 * S; i += 256) {
        int l = i / S, s = i - l * S;
        float acc = 0.f;
        #pragma unroll 16
        for (int e = 0; e < 64; e++) acc += qs[l * 64 + e] * kv[s * 64 + e];
        sc[i] = acc * scale;
    }
    __syncthreads();

    int warp = tid >> 5, lane = tid & 31;
    for (int l = warp; l < 25; l += 8) {
        float mx = -1e30f;
        for (int s = lane; s < S; s += 32) mx = fmaxf(mx, sc[l * S + s]);
        #pragma unroll
        for (int o = 16; o; o >>= 1) mx = fmaxf(mx, __shfl_xor_sync(~0u, mx, o));
        float sum = 0.f;
        for (int s = lane; s < S; s += 32) {
            float e = __expf(sc[l * S + s] - mx);
            sc[l * S + s] = e; sum += e;
        }
        #pragma unroll
        for (int o = 16; o; o >>= 1) sum += __shfl_xor_sync(~0u, sum, o);
        float inv = __fdividef(1.f, sum);
        for (int s = lane; s < S; s += 32) sc[l * S + s] *= inv;
    }
    __syncthreads();

    for (int i = tid; i < S * 64; i += 256) kv[i] = Vp[kbase + (size_t)(i >> 6) * 512 + (i & 63)];
    __syncthreads();

    for (int i = tid; i < 25 * 64; i += 256) {
        int l = i >> 6, e = i & 63;
        float acc = 0.f;
        for (int s = 0; s < S; s++) acc += sc[l * S + s] * kv[s * 64 + e];
        O[qbase + (size_t)l * 512 + e] = acc;
    }
}

// ---------------- LayerNorm over rows of 512 (warp per row) ------------------
__global__ void __launch_bounds__(256) ln_kernel(
    const float* __restrict__ in, const float* __restrict__ g,
    const float* __restrict__ bb, float* __restrict__ out, int M)
{
    int row = blockIdx.x * 8 + (threadIdx.x >> 5);
    int lane = threadIdx.x & 31;
    if (row >= M) return;
    const float* p = in + (size_t)row * 512;
    float v[16];
    float s = 0.f, s2 = 0.f;
    #pragma unroll
    for (int i = 0; i < 16; i++) {
        v[i] = p[lane + 32 * i];
        s += v[i]; s2 += v[i] * v[i];
    }
    #pragma unroll
    for (int o = 16; o; o >>= 1) {
        s  += __shfl_xor_sync(~0u, s,  o);
        s2 += __shfl_xor_sync(~0u, s2, o);
    }
    float mean = s * (1.f / 512.f);
    float var  = s2 * (1.f / 512.f) - mean * mean;
    float rstd = rsqrtf(var + 1e-5f);
    float* q = out + (size_t)row * 512;
    #pragma unroll
    for (int i = 0; i < 16; i++) {
        int d = lane + 32 * i;
        q[d] = (v[i] - mean) * rstd * g[d] + bb[d];
    }
}

// ---------------- tiled transposes -------------------------------------------
__global__ void transpose_in_kernel(const float* __restrict__ in, float* __restrict__ out) {
    __shared__ float tile[32][33];
    int tx = threadIdx.x, ty = threadIdx.y;
    int t0 = blockIdx.x * 32, b0 = blockIdx.y * 32, k = blockIdx.z;
    #pragma unroll
    for (int i = 0; i < 4; i++)
        tile[ty + 8 * i][tx] = in[(size_t)(b0 + ty + 8 * i) * 12800 + k * 512 + t0 + tx];
    __syncthreads();
    #pragma unroll
    for (int i = 0; i < 4; i++)
        out[(size_t)(t0 + ty + 8 * i) * 3200 + k * 128 + b0 + tx] = tile[tx][ty + 8 * i];
}
__global__ void transpose_out_kernel(const float* __restrict__ in, float* __restrict__ out) {
    __shared__ float tile[32][33];
    int tx = threadIdx.x, ty = threadIdx.y;
    int c0 = blockIdx.x * 32, b0 = blockIdx.y * 32, l = blockIdx.z;
    #pragma unroll
    for (int i = 0; i < 4; i++)
        tile[ty + 8 * i][tx] = in[(size_t)(c0 + ty + 8 * i) * 3200 + l * 128 + b0 + tx];
    __syncthreads();
    #pragma unroll
    for (int i = 0; i < 4; i++)
        out[(size_t)((b0 + ty + 8 * i) * 25 + l) * 512 + c0 + tx] = tile[tx][ty + 8 * i];
}

__global__ void zero_flags_kernel() {
    int i = blockIdx.x * 256 + threadIdx.x;
    if (i < 33 * 4 * 32) g_flags[i] = 0;
}

DEVF void spinwait(const int* p, int need) {
    int v;
    do {
        asm volatile("ld.acquire.gpu.global.b32 %0, [%1];" : "=r"(v) : "l"(p) : "memory");
    } while (v < need);
}

// ---------------- LSTM wavefront: 128 blocks = 32 layers x 4 chunks ----------
#define GSTR 36
__global__ void __launch_bounds__(256, 1) lstm_wave_kernel(
    const float* __restrict__ Wih, const float* __restrict__ Whh,
    const float* __restrict__ bih, const float* __restrict__ bhh)
{
    int layer = blockIdx.x & 31;
    int chunk = blockIdx.x >> 5;
    int b0 = chunk * 32;
    const float* in  = g_Y + (size_t)layer * YSTRIDE;
    float* outp      = g_Y + (size_t)(layer + 1) * YSTRIDE;
    const int* inflag = g_flags + (layer * 4 + chunk) * 32;
    int* outflag      = g_flags + ((layer + 1) * 4 + chunk) * 32;

    __shared__ __align__(16) float xbuf[2][25][32];
    __shared__ __align__(16) float hbuf[25][32];
    __shared__ __align__(16) float gates[100][GSTR];

    int tid = threadIdx.x;
    int warp = tid >> 5;

    int j = tid >> 1, bbase = (tid & 1) << 4;
    ull wsp[50];
    ull bias2 = 0ull;
    if (tid < 200) {
        const float* wi = Wih + (size_t)layer * 2500 + j * 25;
        const float* wh = Whh + (size_t)layer * 2500 + j * 25;
        #pragma unroll
        for (int k = 0; k < 25; k++) { wsp[k] = splat2(wi[k]); wsp[25 + k] = splat2(wh[k]); }
        bias2 = splat2(bih[layer * 100 + j] + bhh[layer * 100 + j]);
    }
    bool isg = (j >= 50 && j < 75);
    int u = tid >> 3, bb = (tid & 7) << 2;
    float4 cst = make_float4(0.f, 0.f, 0.f, 0.f);

    for (int i = tid; i < 800; i += 256) hbuf[i >> 5][i & 31] = 0.f;

    if (warp == 7) {
        if (layer > 0 && tid == 224) spinwait(inflag, 1);
        __syncwarp();
        int lane = tid - 224;
        #pragma unroll
        for (int k = 0; k < 25; k++) xbuf[0][k][lane] = in[k * 128 + b0 + lane];
    }
    __syncthreads();

    for (int t = 0; t < 512; t++) {
        int par = t & 1;
        if (tid < 200) {
            ull acc[8];
            #pragma unroll
            for (int q = 0; q < 8; q++) acc[q] = bias2;
            #pragma unroll
            for (int k = 0; k < 25; k++) {
                ull wp = wsp[k];
                const ulonglong2* row = (const ulonglong2*)&xbuf[par][k][bbase];
                ulonglong2 p0 = row[0], p1 = row[1], p2 = row[2], p3 = row[3];
                fma2(acc[0], p0.x, wp); fma2(acc[1], p0.y, wp);
                fma2(acc[2], p1.x, wp); fma2(acc[3], p1.y, wp);
                fma2(acc[4], p2.x, wp); fma2(acc[5], p2.y, wp);
                fma2(acc[6], p3.x, wp); fma2(acc[7], p3.y, wp);
            }
            #pragma unroll
            for (int k = 0; k < 25; k++) {
                ull wp = wsp[25 + k];
                const ulonglong2* row = (const ulonglong2*)&hbuf[k][bbase];
                ulonglong2 p0 = row[0], p1 = row[1], p2 = row[2], p3 = row[3];
                fma2(acc[0], p0.x, wp); fma2(acc[1], p0.y, wp);
                fma2(acc[2], p1.x, wp); fma2(acc[3], p1.y, wp);
                fma2(acc[4], p2.x, wp); fma2(acc[5], p2.y, wp);
                fma2(acc[6], p3.x, wp); fma2(acc[7], p3.y, wp);
            }
            float g16[16];
            #pragma unroll
            for (int q = 0; q < 8; q++) {
                float2 f = unpack2(acc[q]);
                g16[2 * q] = f.x; g16[2 * q + 1] = f.y;
            }
            #pragma unroll
            for (int i = 0; i < 16; i++) g16[i] = isg ? tanh_fast(g16[i]) : sig_fast(g16[i]);
            float4* gp = (float4*)&gates[j][bbase];
            gp[0] = make_float4(g16[0],  g16[1],  g16[2],  g16[3]);
            gp[1] = make_float4(g16[4],  g16[5],  g16[6],  g16[7]);
            gp[2] = make_float4(g16[8],  g16[9],  g16[10], g16[11]);
            gp[3] = make_float4(g16[12], g16[13], g16[14], g16[15]);
        } else if (warp == 7) {
            if (t < 511) {
                if (layer > 0 && tid == 224) spinwait(inflag, t + 2);
                __syncwarp();
                int lane = tid - 224;
                const float* src = in + (size_t)(t + 1) * 3200 + b0;
                #pragma unroll
                for (int k = 0; k < 25; k++) xbuf[par ^ 1][k][lane] = src[k * 128 + lane];
            }
        }
        __syncthreads();

        if (tid < 200) {
            float4 gi = *(const float4*)&gates[u     ][bb];
            float4 gf = *(const float4*)&gates[u + 25][bb];
            float4 gg = *(const float4*)&gates[u + 50][bb];
            float4 go = *(const float4*)&gates[u + 75][bb];
            cst.x = gf.x * cst.x + gi.x * gg.x;
            cst.y = gf.y * cst.y + gi.y * gg.y;
            cst.z = gf.z * cst.z + gi.z * gg.z;
            cst.w = gf.w * cst.w + gi.w * gg.w;
            float4 h4 = make_float4(go.x * tanh_fast(cst.x), go.y * tanh_fast(cst.y),
                                    go.z * tanh_fast(cst.z), go.w * tanh_fast(cst.w));
            *(float4*)&hbuf[u][bb] = h4;
            *(float4*)(outp + (size_t)t * 3200 + u * 128 + b0 + bb) = h4;
        }
        __syncthreads();
        if (tid == 0) {
            int nv = t + 1;
            asm volatile("st.release.gpu.global.b32 [%0], %1;" :: "l"(outflag), "r"(nv) : "memory");
        }
    }
}

// ---------------- launcher ---------------------------------------------------
extern "C" void kernel_launch(void* const* d_in, const int* in_sizes, int n_in,
                              void* d_out, int out_size)
{
    const float* x     = (const float*)d_in[0];
    const float* cross = (const float*)d_in[1];
    const float* Wq_s = (const float*)d_in[2];  const float* bq_s = (const float*)d_in[3];
    const float* Wk_s = (const float*)d_in[4];  const float* bk_s = (const float*)d_in[5];
    const float* Wv_s = (const float*)d_in[6];  const float* bv_s = (const float*)d_in[7];
    const float* Wo_s = (const float*)d_in[8];  const float* bo_s = (const float*)d_in[9];
    const float* Wq_c = (const float*)d_in[10]; const float* bq_c = (const float*)d_in[11];
    const float* Wk_c = (const float*)d_in[12]; const float* bk_c = (const float*)d_in[13];
    const float* Wv_c = (const float*)d_in[14]; const float* bv_c = (const float*)d_in[15];
    const float* Wo_c = (const float*)d_in[16]; const float* bo_c = (const float*)d_in[17];
    const float* g1 = (const float*)d_in[18]; const float* b1 = (const float*)d_in[19];
    const float* g2 = (const float*)d_in[20]; const float* b2 = (const float*)d_in[21];
    const float* g3 = (const float*)d_in[22]; const float* b3 = (const float*)d_in[23];
    const float* W_ih = (const float*)d_in[24];
    const float* W_hh = (const float*)d_in[25];
    const float* b_ih = (const float*)d_in[26];
    const float* b_hh = (const float*)d_in[27];
    const float* Wc = (const float*)d_in[28]; const float* bc = (const float*)d_in[29];
    float* out = (float*)d_out;

    float *gq, *gk, *gv, *gctx, *gx1, *gx2, *gtmp, *gyt, *gY;
    cudaGetSymbolAddress((void**)&gq,   g_q);
    cudaGetSymbolAddress((void**)&gk,   g_k);
    cudaGetSymbolAddress((void**)&gv,   g_v);
    cudaGetSymbolAddress((void**)&gctx, g_ctx);
    cudaGetSymbolAddress((void**)&gx1,  g_x1);
    cudaGetSymbolAddress((void**)&gx2,  g_x2);
    cudaGetSymbolAddress((void**)&gtmp, g_tmp);
    cudaGetSymbolAddress((void**)&gyt,  g_yt);
    cudaGetSymbolAddress((void**)&gY,   g_Y);

    const int M1 = 3200;    // B*L
    zero_flags_kernel<<<17, 256>>>();

    // ---- self attention ----
    {
        GemmSet s = {{Wq_s, Wk_s, Wv_s}, {bq_s, bk_s, bv_s},
                     {nullptr, nullptr, nullptr}, {gq, gk, gv}};
        gemm_tc_kernel<false><<<dim3(50, 8, 3), 128>>>(x, s);
    }
    attn_kernel<<<128 * 8, 256>>>(gq, gk, gv, gctx, 25);
    {
        GemmSet s = {{Wo_s, nullptr, nullptr}, {bo_s, nullptr, nullptr},
                     {x, nullptr, nullptr}, {gtmp, nullptr, nullptr}};
        gemm_tc_kernel<false><<<dim3(50, 8, 1), 128>>>(gctx, s);
    }
    ln_kernel<<<M1 / 8, 256>>>(gtmp, g1, b1, gx1, M1);

    // ---- cross attention ----
    {
        GemmSet s = {{Wq_c, nullptr, nullptr}, {bq_c, nullptr, nullptr},
                     {nullptr, nullptr, nullptr}, {gq, nullptr, nullptr}};
        gemm_tc_kernel<false><<<dim3(50, 8, 1), 128>>>(gx1, s);
    }
    {
        GemmSet s = {{Wk_c, Wv_c, nullptr}, {bk_c, bv_c, nullptr},
                     {nullptr, nullptr, nullptr}, {gk, gv, nullptr}};
        gemm_tc_kernel<false><<<dim3(192, 8, 2), 128>>>(cross, s);
    }
    attn_kernel<<<128 * 8, 256>>>(gq, gk, gv, gctx, 96);
    {
        GemmSet s = {{Wo_c, nullptr, nullptr}, {bo_c, nullptr, nullptr},
                     {gx1, nullptr, nullptr}, {gtmp, nullptr, nullptr}};
        gemm_tc_kernel<false><<<dim3(50, 8, 1), 128>>>(gctx, s);
    }
    ln_kernel<<<M1 / 8, 256>>>(gtmp, g2, b2, gx2, M1);

    // ---- LSTM wavefront over feature axis ----
    transpose_in_kernel<<<dim3(16, 4, 25), dim3(32, 8)>>>(gx2, gY);
    lstm_wave_kernel<<<128, 256>>>(W_ih, W_hh, b_ih, b_hh);

    // ---- pointwise conv + residual + final LN ----
    transpose_out_kernel<<<dim3(16, 4, 25), dim3(32, 8)>>>(gY + 32ull * YSTRIDE, gyt);
    {
        GemmSet s = {{Wc, nullptr, nullptr}, {bc, nullptr, nullptr},
                     {gx2, nullptr, nullptr}, {gtmp, nullptr, nullptr}};
        gemm_tc_kernel<true><<<dim3(50, 8, 1), 128>>>(gyt, s);
    }
    ln_kernel<<<M1 / 8, 256>>>(gtmp, g3, b3, out, M1);
}

// round 8
// speedup vs baseline: 2.0185x; 1.0132x over previous
#include <cuda_runtime.h>
#include <cstddef>

#define DEVF __device__ __forceinline__
typedef unsigned long long ull;

// ---------------- scratch (device globals; no allocations allowed) ----------
__device__ float g_q  [3200 * 512];
__device__ float g_k  [12288 * 512];
__device__ float g_v  [12288 * 512];
__device__ float g_ctx[3200 * 512];
__device__ float g_x1 [3200 * 512];
__device__ float g_x2 [3200 * 512];
__device__ float g_tmp[3200 * 512];
__device__ float g_yt [3200 * 512];

// LSTM wavefront buffers: Y[l][t][k][b], l = 0..32, t<512, k<25, b<128
#define YSTRIDE 1638400   // 512*25*128
__device__ float g_Y[33ull * YSTRIDE];
__device__ int   g_flags[33 * 4 * 32];   // (layer,chunk) progress, 128B padded

// ---------------- f32x2 packed helpers (LSTM) --------------------------------
DEVF void fma2(ull& d, ull a, ull b) {
    asm("fma.rn.f32x2 %0, %1, %2, %0;" : "+l"(d) : "l"(a), "l"(b));
}
DEVF ull splat2(float x) {
    ull r; unsigned ix = __float_as_uint(x);
    asm("mov.b64 %0, {%1, %1};" : "=l"(r) : "r"(ix));
    return r;
}
DEVF float2 unpack2(ull v) {
    unsigned lo, hi;
    asm("mov.b64 {%0, %1}, %2;" : "=r"(lo), "=r"(hi) : "l"(v));
    return make_float2(__uint_as_float(lo), __uint_as_float(hi));
}

// ---------------- activations ------------------------------------------------
DEVF float tanh_fast(float x) {
    float y; asm("tanh.approx.f32 %0, %1;" : "=f"(y) : "f"(x)); return y;
}
DEVF float sig_fast(float x) { return fmaf(tanh_fast(0.5f * x), 0.5f, 0.5f); }

// ---------------- tf32 helpers -----------------------------------------------
DEVF unsigned totf(float x) {
    unsigned r; asm("cvt.rna.tf32.f32 %0, %1;" : "=r"(r) : "f"(x)); return r;
}
DEVF uint4 totf4(float4 v) { return make_uint4(totf(v.x), totf(v.y), totf(v.z), totf(v.w)); }

DEVF void mma_tf32(float* c, const unsigned* a, unsigned b0, unsigned b1) {
    asm("mma.sync.aligned.m16n8k8.row.col.f32.tf32.tf32.f32 "
        "{%0,%1,%2,%3}, {%4,%5,%6,%7}, {%8,%9}, {%0,%1,%2,%3};"
        : "+f"(c[0]), "+f"(c[1]), "+f"(c[2]), "+f"(c[3])
        : "r"(a[0]), "r"(a[1]), "r"(a[2]), "r"(a[3]), "r"(b0), "r"(b1));
}

// ---------------- tf32 tensor-core GEMM --------------------------------------
// C[.,512] = A[.,512] @ W (+bias)(+res). TRANSW: W stored [N,K] else [K,N].
// Tile 128x64xBK16, 128 threads = 2(m)x2(n) warps, each warp 64x32.
template<bool TRANSW>
DEVF void gemm_tc_core(const float* __restrict__ A, const float* __restrict__ W,
                       const float* __restrict__ bias, const float* __restrict__ res,
                       float* __restrict__ C)
{
    __shared__ __align__(16) unsigned As[2][128][20];  // [m][k], pad->conflict-free frags
    __shared__ __align__(16) unsigned Bs[2][16][72];   // [k][n], pad->conflict-free frags

    int tid = threadIdx.x;
    int bm = blockIdx.x * 128, bn = blockIdx.y * 64;
    int lane = tid & 31, wid = tid >> 5;
    int wm = wid & 1, wn = wid >> 1;           // warp tile 64(m) x 32(n)
    int g = lane >> 2, tg = lane & 3;

    float acc[4][4][4];
    #pragma unroll
    for (int i = 0; i < 4; i++)
        #pragma unroll
        for (int j = 0; j < 4; j++)
            #pragma unroll
            for (int q = 0; q < 4; q++) acc[i][j][q] = 0.f;

    // A staging: thread = row tid (0..127), all 16 k of the tile
    const float* Arow = A + (size_t)(bm + tid) * 512;
    // B staging (!TRANSW): kk row 0..15, nn = 8-col group
    int kk = tid >> 3, nn = (tid & 7) * 8;
    // B staging (TRANSW): nr row 0..63, kc = 8-k group
    int nr = tid >> 1, kc = (tid & 1) * 8;

    float4 aT[4], bT0, bT1;

    // ---- prologue: fetch + store k-tile 0 ----
    #pragma unroll
    for (int j = 0; j < 4; j++) aT[j] = *(const float4*)(Arow + 4 * j);
    if (!TRANSW) {
        bT0 = *(const float4*)(W + (size_t)kk * 512 + bn + nn);
        bT1 = *(const float4*)(W + (size_t)kk * 512 + bn + nn + 4);
    } else {
        bT0 = *(const float4*)(W + (size_t)(bn + nr) * 512 + kc);
        bT1 = *(const float4*)(W + (size_t)(bn + nr) * 512 + kc + 4);
    }
    #pragma unroll
    for (int j = 0; j < 4; j++) *(uint4*)&As[0][tid][4 * j] = totf4(aT[j]);
    if (!TRANSW) {
        *(uint4*)&Bs[0][kk][nn]     = totf4(bT0);
        *(uint4*)&Bs[0][kk][nn + 4] = totf4(bT1);
    } else {
        Bs[0][kc + 0][nr] = totf(bT0.x); Bs[0][kc + 1][nr] = totf(bT0.y);
        Bs[0][kc + 2][nr] = totf(bT0.z); Bs[0][kc + 3][nr] = totf(bT0.w);
        Bs[0][kc + 4][nr] = totf(bT1.x); Bs[0][kc + 5][nr] = totf(bT1.y);
        Bs[0][kc + 6][nr] = totf(bT1.z); Bs[0][kc + 7][nr] = totf(bT1.w);
    }
    __syncthreads();

    int am0 = wm * 64 + g;
    int bn0 = wn * 32 + g;

    for (int it = 0; it < 32; it++) {
        int buf = it & 1;
        if (it < 31) {
            int k0 = (it + 1) * 16;
            #pragma unroll
            for (int j = 0; j < 4; j++) aT[j] = *(const float4*)(Arow + k0 + 4 * j);
            if (!TRANSW) {
                bT0 = *(const float4*)(W + (size_t)(k0 + kk) * 512 + bn + nn);
                bT1 = *(const float4*)(W + (size_t)(k0 + kk) * 512 + bn + nn + 4);
            } else {
                bT0 = *(const float4*)(W + (size_t)(bn + nr) * 512 + k0 + kc);
                bT1 = *(const float4*)(W + (size_t)(bn + nr) * 512 + k0 + kc + 4);
            }
        }

        #pragma unroll
        for (int ks = 0; ks < 2; ks++) {
            int klo = ks * 8 + tg;
            unsigned afr[4][4];
            #pragma unroll
            for (int mf = 0; mf < 4; mf++) {
                int m = am0 + mf * 16;
                afr[mf][0] = As[buf][m][klo];
                afr[mf][1] = As[buf][m + 8][klo];
                afr[mf][2] = As[buf][m][klo + 4];
                afr[mf][3] = As[buf][m + 8][klo + 4];
            }
            #pragma unroll
            for (int nf = 0; nf < 4; nf++) {
                unsigned b0 = Bs[buf][klo][bn0 + nf * 8];
                unsigned b1 = Bs[buf][klo + 4][bn0 + nf * 8];
                #pragma unroll
                for (int mf = 0; mf < 4; mf++)
                    mma_tf32(acc[mf][nf], afr[mf], b0, b1);
            }
        }

        if (it < 31) {
            int nb = buf ^ 1;
            #pragma unroll
            for (int j = 0; j < 4; j++) *(uint4*)&As[nb][tid][4 * j] = totf4(aT[j]);
            if (!TRANSW) {
                *(uint4*)&Bs[nb][kk][nn]     = totf4(bT0);
                *(uint4*)&Bs[nb][kk][nn + 4] = totf4(bT1);
            } else {
                Bs[nb][kc + 0][nr] = totf(bT0.x); Bs[nb][kc + 1][nr] = totf(bT0.y);
                Bs[nb][kc + 2][nr] = totf(bT0.z); Bs[nb][kc + 3][nr] = totf(bT0.w);
                Bs[nb][kc + 4][nr] = totf(bT1.x); Bs[nb][kc + 5][nr] = totf(bT1.y);
                Bs[nb][kc + 6][nr] = totf(bT1.z); Bs[nb][kc + 7][nr] = totf(bT1.w);
            }
        }
        __syncthreads();
    }

    // ---- epilogue ----
    #pragma unroll
    for (int nf = 0; nf < 4; nf++) {
        int col = bn + wn * 32 + nf * 8 + 2 * tg;
        float2 bv = *(const float2*)(bias + col);
        #pragma unroll
        for (int mf = 0; mf < 4; mf++) {
            int row = bm + wm * 64 + mf * 16 + g;
            float2 v0 = make_float2(acc[mf][nf][0] + bv.x, acc[mf][nf][1] + bv.y);
            float2 v1 = make_float2(acc[mf][nf][2] + bv.x, acc[mf][nf][3] + bv.y);
            if (res) {
                float2 r0 = *(const float2*)(res + (size_t)row * 512 + col);
                float2 r1 = *(const float2*)(res + (size_t)(row + 8) * 512 + col);
                v0.x += r0.x; v0.y += r0.y; v1.x += r1.x; v1.y += r1.y;
            }
            *(float2*)(C + (size_t)row * 512 + col) = v0;
            *(float2*)(C + (size_t)(row + 8) * 512 + col) = v1;
        }
    }
}

struct GemmSet {
    const float* W[3];
    const float* b[3];
    const float* r[3];
    float*       C[3];
};

template<bool TRANSW>
__global__ void __launch_bounds__(128, 3) gemm_tc_kernel(const float* __restrict__ A, GemmSet s) {
    int z = blockIdx.z;
    gemm_tc_core<TRANSW>(A, s.W[z], s.b[z], s.r[z], s.C[z]);
}

// ---------------- attention core: one block per (b, h), 256 threads ---------
__global__ void __launch_bounds__(256) attn_kernel(
    const float* __restrict__ Q, const float* __restrict__ Kp,
    const float* __restrict__ Vp, float* __restrict__ O, int S)
{
    __shared__ float qs[25 * 64];
    __shared__ float kv[96 * 64];
    __shared__ float sc[25 * 96];
    int b = blockIdx.x >> 3, h = blockIdx.x & 7;
    int tid = threadIdx.x;
    const float scale = 0.125f;
    size_t qbase = (size_t)b * 25 * 512 + h * 64;
    size_t kbase = (size_t)b * S  * 512 + h * 64;

    for (int i = tid; i < 25 * 64; i += 256) qs[i] = Q[qbase + (size_t)(i >> 6) * 512 + (i & 63)];
    for (int i = tid; i < S  * 64; i += 256) kv[i] = Kp[kbase + (size_t)(i >> 6) * 512 + (i & 63)];
    __syncthreads();

    for (int i = tid; i < 25 * S; i += 256) {
        int l = i / S, s = i - l * S;
        float acc = 0.f;
        #pragma unroll 16
        for (int e = 0; e < 64; e++) acc += qs[l * 64 + e] * kv[s * 64 + e];
        sc[i] = acc * scale;
    }
    __syncthreads();

    int warp = tid >> 5, lane = tid & 31;
    for (int l = warp; l < 25; l += 8) {
        float mx = -1e30f;
        for (int s = lane; s < S; s += 32) mx = fmaxf(mx, sc[l * S + s]);
        #pragma unroll
        for (int o = 16; o; o >>= 1) mx = fmaxf(mx, __shfl_xor_sync(~0u, mx, o));
        float sum = 0.f;
        for (int s = lane; s < S; s += 32) {
            float e = __expf(sc[l * S + s] - mx);
            sc[l * S + s] = e; sum += e;
        }
        #pragma unroll
        for (int o = 16; o; o >>= 1) sum += __shfl_xor_sync(~0u, sum, o);
        float inv = __fdividef(1.f, sum);
        for (int s = lane; s < S; s += 32) sc[l * S + s] *= inv;
    }
    __syncthreads();

    for (int i = tid; i < S * 64; i += 256) kv[i] = Vp[kbase + (size_t)(i >> 6) * 512 + (i & 63)];
    __syncthreads();

    for (int i = tid; i < 25 * 64; i += 256) {
        int l = i >> 6, e = i & 63;
        float acc = 0.f;
        for (int s = 0; s < S; s++) acc += sc[l * S + s] * kv[s * 64 + e];
        O[qbase + (size_t)l * 512 + e] = acc;
    }
}

// ---------------- LayerNorm over rows of 512 (warp per row) ------------------
__global__ void __launch_bounds__(256) ln_kernel(
    const float* __restrict__ in, const float* __restrict__ g,
    const float* __restrict__ bb, float* __restrict__ out, int M)
{
    int row = blockIdx.x * 8 + (threadIdx.x >> 5);
    int lane = threadIdx.x & 31;
    if (row >= M) return;
    const float* p = in + (size_t)row * 512;
    float v[16];
    float s = 0.f, s2 = 0.f;
    #pragma unroll
    for (int i = 0; i < 16; i++) {
        v[i] = p[lane + 32 * i];
        s += v[i]; s2 += v[i] * v[i];
    }
    #pragma unroll
    for (int o = 16; o; o >>= 1) {
        s  += __shfl_xor_sync(~0u, s,  o);
        s2 += __shfl_xor_sync(~0u, s2, o);
    }
    float mean = s * (1.f / 512.f);
    float var  = s2 * (1.f / 512.f) - mean * mean;
    float rstd = rsqrtf(var + 1e-5f);
    float* q = out + (size_t)row * 512;
    #pragma unroll
    for (int i = 0; i < 16; i++) {
        int d = lane + 32 * i;
        q[d] = (v[i] - mean) * rstd * g[d] + bb[d];
    }
}

// ---------------- tiled transposes -------------------------------------------
__global__ void transpose_in_kernel(const float* __restrict__ in, float* __restrict__ out) {
    __shared__ float tile[32][33];
    int tx = threadIdx.x, ty = threadIdx.y;
    int t0 = blockIdx.x * 32, b0 = blockIdx.y * 32, k = blockIdx.z;
    #pragma unroll
    for (int i = 0; i < 4; i++)
        tile[ty + 8 * i][tx] = in[(size_t)(b0 + ty + 8 * i) * 12800 + k * 512 + t0 + tx];
    __syncthreads();
    #pragma unroll
    for (int i = 0; i < 4; i++)
        out[(size_t)(t0 + ty + 8 * i) * 3200 + k * 128 + b0 + tx] = tile[tx][ty + 8 * i];
}
__global__ void transpose_out_kernel(const float* __restrict__ in, float* __restrict__ out) {
    __shared__ float tile[32][33];
    int tx = threadIdx.x, ty = threadIdx.y;
    int c0 = blockIdx.x * 32, b0 = blockIdx.y * 32, l = blockIdx.z;
    #pragma unroll
    for (int i = 0; i < 4; i++)
        tile[ty + 8 * i][tx] = in[(size_t)(c0 + ty + 8 * i) * 3200 + l * 128 + b0 + tx];
    __syncthreads();
    #pragma unroll
    for (int i = 0; i < 4; i++)
        out[(size_t)((b0 + ty + 8 * i) * 25 + l) * 512 + c0 + tx] = tile[tx][ty + 8 * i];
}

__global__ void zero_flags_kernel() {
    int i = blockIdx.x * 256 + threadIdx.x;
    if (i < 33 * 4 * 32) g_flags[i] = 0;
}

DEVF void spinwait(const int* p, int need) {
    int v;
    do {
        asm volatile("ld.acquire.gpu.global.b32 %0, [%1];" : "=r"(v) : "l"(p) : "memory");
    } while (v < need);
}

// ---------------- LSTM wavefront: 128 blocks = 32 layers x 4 chunks ----------
// Fused single-phase: thread (u, 4 batches) computes all 4 gates + cell update.
// Weights pre-splatted (f32x2) in dynamic smem. hbuf double-buffered.
// ONE barrier per step. Warp 7 = IO (flag wait + x prefetch).
#define LSTM_SMEM ((2500 + 2500 + 100) * 8 + (1600 + 1600) * 4)
__global__ void __launch_bounds__(256, 1) lstm_wave_kernel(
    const float* __restrict__ Wih, const float* __restrict__ Whh,
    const float* __restrict__ bih, const float* __restrict__ bhh)
{
    extern __shared__ __align__(16) char smraw[];
    ull*   wih_p  = (ull*)smraw;              // [25k][25u][4q]
    ull*   whh_p  = wih_p + 2500;
    ull*   bias_p = whh_p + 2500;             // [25u][4q]
    float* xb     = (float*)(bias_p + 100);   // [2][25][32]
    float* hb     = xb + 1600;                // [2][25][32]

    int layer = blockIdx.x & 31;
    int chunk = blockIdx.x >> 5;
    int b0 = chunk * 32;
    const float* in  = g_Y + (size_t)layer * YSTRIDE;
    float* outp      = g_Y + (size_t)(layer + 1) * YSTRIDE;
    const int* inflag = g_flags + (layer * 4 + chunk) * 32;
    int* outflag      = g_flags + ((layer + 1) * 4 + chunk) * 32;

    int tid = threadIdx.x;
    int warp = tid >> 5;
    int u = tid >> 3, bb = (tid & 7) << 2;

    // ---- prepack weights (splatted) + biases + zero h ----
    {
        const float* WI = Wih + (size_t)layer * 2500;
        const float* WH = Whh + (size_t)layer * 2500;
        for (int idx = tid; idx < 2500; idx += 256) {
            int k = idx / 100; int r = idx - k * 100;
            int uu = r >> 2, q = r & 3;
            int row = q * 25 + uu;
            wih_p[idx] = splat2(WI[row * 25 + k]);
            whh_p[idx] = splat2(WH[row * 25 + k]);
        }
        for (int idx = tid; idx < 100; idx += 256) {
            int uu = idx >> 2, q = idx & 3;
            int row = q * 25 + uu;
            bias_p[idx] = splat2(bih[layer * 100 + row] + bhh[layer * 100 + row]);
        }
        for (int i = tid; i < 1600; i += 256) hb[i] = 0.f;
    }
    __syncthreads();

    ull bq0 = 0, bq1 = 0, bq2 = 0, bq3 = 0;
    if (tid < 200) {
        bq0 = bias_p[u * 4 + 0]; bq1 = bias_p[u * 4 + 1];
        bq2 = bias_p[u * 4 + 2]; bq3 = bias_p[u * 4 + 3];
    }
    float4 cst = make_float4(0.f, 0.f, 0.f, 0.f);

    // prologue: load x_0
    if (warp == 7) {
        if (layer > 0 && tid == 224) spinwait(inflag, 1);
        __syncwarp();
        int lane = tid - 224;
        #pragma unroll
        for (int k = 0; k < 25; k++) xb[k * 32 + lane] = in[k * 128 + b0 + lane];
    }
    __syncthreads();

    const ulonglong2* wi2 = (const ulonglong2*)wih_p + u * 2;
    const ulonglong2* wh2 = (const ulonglong2*)whh_p + u * 2;

    for (int t = 0; t < 512; t++) {
        int par = t & 1;
        if (tid < 200) {
            ull a00 = bq0, a01 = bq0, a10 = bq1, a11 = bq1;
            ull a20 = bq2, a21 = bq2, a30 = bq3, a31 = bq3;
            const float* xrow = xb + par * 800 + bb;
            const float* hrow = hb + par * 800 + bb;
            #pragma unroll
            for (int k = 0; k < 25; k++) {
                ulonglong2 xv = *(const ulonglong2*)(xrow + k * 32);
                ulonglong2 hv = *(const ulonglong2*)(hrow + k * 32);
                ulonglong2 wi01 = wi2[k * 50], wi23 = wi2[k * 50 + 1];
                ulonglong2 wh01 = wh2[k * 50], wh23 = wh2[k * 50 + 1];
                fma2(a00, xv.x, wi01.x); fma2(a01, xv.y, wi01.x);
                fma2(a10, xv.x, wi01.y); fma2(a11, xv.y, wi01.y);
                fma2(a20, xv.x, wi23.x); fma2(a21, xv.y, wi23.x);
                fma2(a30, xv.x, wi23.y); fma2(a31, xv.y, wi23.y);
                fma2(a00, hv.x, wh01.x); fma2(a01, hv.y, wh01.x);
                fma2(a10, hv.x, wh01.y); fma2(a11, hv.y, wh01.y);
                fma2(a20, hv.x, wh23.x); fma2(a21, hv.y, wh23.x);
                fma2(a30, hv.x, wh23.y); fma2(a31, hv.y, wh23.y);
            }
            float2 iA = unpack2(a00), iB = unpack2(a01);
            float2 fA = unpack2(a10), fB = unpack2(a11);
            float2 gA = unpack2(a20), gB = unpack2(a21);
            float2 oA = unpack2(a30), oB = unpack2(a31);
            float i0 = sig_fast(iA.x), i1 = sig_fast(iA.y), i2 = sig_fast(iB.x), i3 = sig_fast(iB.y);
            float f0 = sig_fast(fA.x), f1 = sig_fast(fA.y), f2 = sig_fast(fB.x), f3 = sig_fast(fB.y);
            float q0 = tanh_fast(gA.x), q1 = tanh_fast(gA.y), q2 = tanh_fast(gB.x), q3 = tanh_fast(gB.y);
            float o0 = sig_fast(oA.x), o1 = sig_fast(oA.y), o2 = sig_fast(oB.x), o3 = sig_fast(oB.y);
            cst.x = f0 * cst.x + i0 * q0;
            cst.y = f1 * cst.y + i1 * q1;
            cst.z = f2 * cst.z + i2 * q2;
            cst.w = f3 * cst.w + i3 * q3;
            float4 h4 = make_float4(o0 * tanh_fast(cst.x), o1 * tanh_fast(cst.y),
                                    o2 * tanh_fast(cst.z), o3 * tanh_fast(cst.w));
            *(float4*)(hb + (par ^ 1) * 800 + u * 32 + bb) = h4;
            *(float4*)(outp + (size_t)t * 3200 + u * 128 + b0 + bb) = h4;
        } else if (warp == 7) {
            if (t < 511) {
                if (layer > 0 && tid == 224) spinwait(inflag, t + 2);
                __syncwarp();
                int lane = tid - 224;
                const float* src = in + (size_t)(t + 1) * 3200 + b0;
                #pragma unroll
                for (int k = 0; k < 25; k++) xb[(par ^ 1) * 800 + k * 32 + lane] = src[k * 128 + lane];
            }
        }
        __syncthreads();
        if (tid == 0) {
            int nv = t + 1;
            asm volatile("st.release.gpu.global.b32 [%0], %1;" :: "l"(outflag), "r"(nv) : "memory");
        }
    }
}

// ---------------- launcher ---------------------------------------------------
extern "C" void kernel_launch(void* const* d_in, const int* in_sizes, int n_in,
                              void* d_out, int out_size)
{
    const float* x     = (const float*)d_in[0];
    const float* cross = (const float*)d_in[1];
    const float* Wq_s = (const float*)d_in[2];  const float* bq_s = (const float*)d_in[3];
    const float* Wk_s = (const float*)d_in[4];  const float* bk_s = (const float*)d_in[5];
    const float* Wv_s = (const float*)d_in[6];  const float* bv_s = (const float*)d_in[7];
    const float* Wo_s = (const float*)d_in[8];  const float* bo_s = (const float*)d_in[9];
    const float* Wq_c = (const float*)d_in[10]; const float* bq_c = (const float*)d_in[11];
    const float* Wk_c = (const float*)d_in[12]; const float* bk_c = (const float*)d_in[13];
    const float* Wv_c = (const float*)d_in[14]; const float* bv_c = (const float*)d_in[15];
    const float* Wo_c = (const float*)d_in[16]; const float* bo_c = (const float*)d_in[17];
    const float* g1 = (const float*)d_in[18]; const float* b1 = (const float*)d_in[19];
    const float* g2 = (const float*)d_in[20]; const float* b2 = (const float*)d_in[21];
    const float* g3 = (const float*)d_in[22]; const float* b3 = (const float*)d_in[23];
    const float* W_ih = (const float*)d_in[24];
    const float* W_hh = (const float*)d_in[25];
    const float* b_ih = (const float*)d_in[26];
    const float* b_hh = (const float*)d_in[27];
    const float* Wc = (const float*)d_in[28]; const float* bc = (const float*)d_in[29];
    float* out = (float*)d_out;

    float *gq, *gk, *gv, *gctx, *gx1, *gx2, *gtmp, *gyt, *gY;
    cudaGetSymbolAddress((void**)&gq,   g_q);
    cudaGetSymbolAddress((void**)&gk,   g_k);
    cudaGetSymbolAddress((void**)&gv,   g_v);
    cudaGetSymbolAddress((void**)&gctx, g_ctx);
    cudaGetSymbolAddress((void**)&gx1,  g_x1);
    cudaGetSymbolAddress((void**)&gx2,  g_x2);
    cudaGetSymbolAddress((void**)&gtmp, g_tmp);
    cudaGetSymbolAddress((void**)&gyt,  g_yt);
    cudaGetSymbolAddress((void**)&gY,   g_Y);

    static int smem_set = 0;
    if (!smem_set) {
        cudaFuncSetAttribute(lstm_wave_kernel,
                             cudaFuncAttributeMaxDynamicSharedMemorySize, LSTM_SMEM);
        smem_set = 1;
    }

    const int M1 = 3200;    // B*L
    zero_flags_kernel<<<17, 256>>>();

    // ---- self attention ----
    {
        GemmSet s = {{Wq_s, Wk_s, Wv_s}, {bq_s, bk_s, bv_s},
                     {nullptr, nullptr, nullptr}, {gq, gk, gv}};
        gemm_tc_kernel<false><<<dim3(25, 8, 3), 128>>>(x, s);
    }
    attn_kernel<<<128 * 8, 256>>>(gq, gk, gv, gctx, 25);
    {
        GemmSet s = {{Wo_s, nullptr, nullptr}, {bo_s, nullptr, nullptr},
                     {x, nullptr, nullptr}, {gtmp, nullptr, nullptr}};
        gemm_tc_kernel<false><<<dim3(25, 8, 1), 128>>>(gctx, s);
    }
    ln_kernel<<<M1 / 8, 256>>>(gtmp, g1, b1, gx1, M1);

    // ---- cross attention ----
    {
        GemmSet s = {{Wq_c, nullptr, nullptr}, {bq_c, nullptr, nullptr},
                     {nullptr, nullptr, nullptr}, {gq, nullptr, nullptr}};
        gemm_tc_kernel<false><<<dim3(25, 8, 1), 128>>>(gx1, s);
    }
    {
        GemmSet s = {{Wk_c, Wv_c, nullptr}, {bk_c, bv_c, nullptr},
                     {nullptr, nullptr, nullptr}, {gk, gv, nullptr}};
        gemm_tc_kernel<false><<<dim3(96, 8, 2), 128>>>(cross, s);
    }
    attn_kernel<<<128 * 8, 256>>>(gq, gk, gv, gctx, 96);
    {
        GemmSet s = {{Wo_c, nullptr, nullptr}, {bo_c, nullptr, nullptr},
                     {gx1, nullptr, nullptr}, {gtmp, nullptr, nullptr}};
        gemm_tc_kernel<false><<<dim3(25, 8, 1), 128>>>(gctx, s);
    }
    ln_kernel<<<M1 / 8, 256>>>(gtmp, g2, b2, gx2, M1);

    // ---- LSTM wavefront over feature axis ----
    transpose_in_kernel<<<dim3(16, 4, 25), dim3(32, 8)>>>(gx2, gY);
    lstm_wave_kernel<<<128, 256, LSTM_SMEM>>>(W_ih, W_hh, b_ih, b_hh);

    // ---- pointwise conv + residual + final LN ----
    transpose_out_kernel<<<dim3(16, 4, 25), dim3(32, 8)>>>(gY + 32ull * YSTRIDE, gyt);
    {
        GemmSet s = {{Wc, nullptr, nullptr}, {bc, nullptr, nullptr},
                     {gx2, nullptr, nullptr}, {gtmp, nullptr, nullptr}};
        gemm_tc_kernel<true><<<dim3(25, 8, 1), 128>>>(gyt, s);
    }
    ln_kernel<<<M1 / 8, 256>>>(gtmp, g3, b3, out, M1);
}

// round 9
// speedup vs baseline: 2.6832x; 1.3293x over previous
#include <cuda_runtime.h>
#include <cstddef>

#define DEVF __device__ __forceinline__
typedef unsigned long long ull;

// ---------------- scratch (device globals; no allocations allowed) ----------
__device__ float g_q  [3200 * 512];
__device__ float g_k  [12288 * 512];
__device__ float g_v  [12288 * 512];
__device__ float g_ctx[3200 * 512];
__device__ float g_x1 [3200 * 512];
__device__ float g_x2 [3200 * 512];
__device__ float g_tmp[3200 * 512];
__device__ float g_yt [3200 * 512];

// LSTM wavefront buffers: Y[l][t][k][b], l = 0..32, t<512, k<25, b<128
#define YSTRIDE 1638400   // 512*25*128
__device__ float g_Y[33ull * YSTRIDE];
__device__ int   g_flags[33 * 4 * 32];   // (layer,chunk) progress, 128B padded

// ---------------- activations ------------------------------------------------
DEVF float tanh_fast(float x) {
    float y; asm("tanh.approx.f32 %0, %1;" : "=f"(y) : "f"(x)); return y;
}
DEVF float sig_fast(float x) { return fmaf(tanh_fast(0.5f * x), 0.5f, 0.5f); }

// ---------------- tf32 helpers -----------------------------------------------
DEVF unsigned totf(float x) {
    unsigned r; asm("cvt.rna.tf32.f32 %0, %1;" : "=r"(r) : "f"(x)); return r;
}
DEVF uint4 totf4(float4 v) { return make_uint4(totf(v.x), totf(v.y), totf(v.z), totf(v.w)); }

DEVF void mma_tf32(float* c, const unsigned* a, unsigned b0, unsigned b1) {
    asm("mma.sync.aligned.m16n8k8.row.col.f32.tf32.tf32.f32 "
        "{%0,%1,%2,%3}, {%4,%5,%6,%7}, {%8,%9}, {%0,%1,%2,%3};"
        : "+f"(c[0]), "+f"(c[1]), "+f"(c[2]), "+f"(c[3])
        : "r"(a[0]), "r"(a[1]), "r"(a[2]), "r"(a[3]), "r"(b0), "r"(b1));
}

// ---------------- tf32 tensor-core GEMM (r7 config: 64x64, 128 thr) ----------
template<bool TRANSW>
DEVF void gemm_tc_core(const float* __restrict__ A, const float* __restrict__ W,
                       const float* __restrict__ bias, const float* __restrict__ res,
                       float* __restrict__ C)
{
    __shared__ __align__(16) unsigned As[2][64][36];
    __shared__ __align__(16) unsigned Bs[2][32][72];

    int tid = threadIdx.x;
    int bm = blockIdx.x * 64, bn = blockIdx.y * 64;
    int lane = tid & 31, wid = tid >> 5;
    int wm = wid & 1, wn = wid >> 1;
    int g = lane >> 2, tg = lane & 3;

    float acc[2][4][4];
    #pragma unroll
    for (int i = 0; i < 2; i++)
        #pragma unroll
        for (int j = 0; j < 4; j++)
            #pragma unroll
            for (int q = 0; q < 4; q++) acc[i][j][q] = 0.f;

    int ar = tid >> 1, ac = (tid & 1) * 16;
    const float* Arow = A + (size_t)(bm + ar) * 512 + ac;
    int kk = tid >> 2, nn = (tid & 3) * 16;
    int nr = tid >> 1, kc = (tid & 1) * 16;

    float4 aT[4], bT[4];

    #pragma unroll
    for (int j = 0; j < 4; j++) aT[j] = *(const float4*)(Arow + 4 * j);
    if (!TRANSW) {
        #pragma unroll
        for (int j = 0; j < 4; j++) bT[j] = *(const float4*)(W + (size_t)kk * 512 + bn + nn + 4 * j);
    } else {
        #pragma unroll
        for (int j = 0; j < 4; j++) bT[j] = *(const float4*)(W + (size_t)(bn + nr) * 512 + kc + 4 * j);
    }
    #pragma unroll
    for (int j = 0; j < 4; j++) *(uint4*)&As[0][ar][ac + 4 * j] = totf4(aT[j]);
    if (!TRANSW) {
        #pragma unroll
        for (int j = 0; j < 4; j++) *(uint4*)&Bs[0][kk][nn + 4 * j] = totf4(bT[j]);
    } else {
        #pragma unroll
        for (int j = 0; j < 4; j++) {
            Bs[0][kc + 4 * j + 0][nr] = totf(bT[j].x);
            Bs[0][kc + 4 * j + 1][nr] = totf(bT[j].y);
            Bs[0][kc + 4 * j + 2][nr] = totf(bT[j].z);
            Bs[0][kc + 4 * j + 3][nr] = totf(bT[j].w);
        }
    }
    __syncthreads();

    int am0 = wm * 32 + g;
    int bn0 = wn * 32 + g;

    for (int it = 0; it < 16; it++) {
        int buf = it & 1;
        if (it < 15) {
            int k0 = (it + 1) * 32;
            #pragma unroll
            for (int j = 0; j < 4; j++) aT[j] = *(const float4*)(Arow + k0 + 4 * j);
            if (!TRANSW) {
                #pragma unroll
                for (int j = 0; j < 4; j++) bT[j] = *(const float4*)(W + (size_t)(k0 + kk) * 512 + bn + nn + 4 * j);
            } else {
                #pragma unroll
                for (int j = 0; j < 4; j++) bT[j] = *(const float4*)(W + (size_t)(bn + nr) * 512 + k0 + kc + 4 * j);
            }
        }

        #pragma unroll
        for (int ks = 0; ks < 4; ks++) {
            int klo = ks * 8 + tg;
            unsigned afr[2][4];
            #pragma unroll
            for (int mf = 0; mf < 2; mf++) {
                int m = am0 + mf * 16;
                afr[mf][0] = As[buf][m][klo];
                afr[mf][1] = As[buf][m + 8][klo];
                afr[mf][2] = As[buf][m][klo + 4];
                afr[mf][3] = As[buf][m + 8][klo + 4];
            }
            #pragma unroll
            for (int nf = 0; nf < 4; nf++) {
                unsigned b0 = Bs[buf][klo][bn0 + nf * 8];
                unsigned b1 = Bs[buf][klo + 4][bn0 + nf * 8];
                mma_tf32(acc[0][nf], afr[0], b0, b1);
                mma_tf32(acc[1][nf], afr[1], b0, b1);
            }
        }

        if (it < 15) {
            int nb = buf ^ 1;
            #pragma unroll
            for (int j = 0; j < 4; j++) *(uint4*)&As[nb][ar][ac + 4 * j] = totf4(aT[j]);
            if (!TRANSW) {
                #pragma unroll
                for (int j = 0; j < 4; j++) *(uint4*)&Bs[nb][kk][nn + 4 * j] = totf4(bT[j]);
            } else {
                #pragma unroll
                for (int j = 0; j < 4; j++) {
                    Bs[nb][kc + 4 * j + 0][nr] = totf(bT[j].x);
                    Bs[nb][kc + 4 * j + 1][nr] = totf(bT[j].y);
                    Bs[nb][kc + 4 * j + 2][nr] = totf(bT[j].z);
                    Bs[nb][kc + 4 * j + 3][nr] = totf(bT[j].w);
                }
            }
        }
        __syncthreads();
    }

    #pragma unroll
    for (int nf = 0; nf < 4; nf++) {
        int col = bn + wn * 32 + nf * 8 + 2 * tg;
        float2 bv = *(const float2*)(bias + col);
        #pragma unroll
        for (int mf = 0; mf < 2; mf++) {
            int row = bm + wm * 32 + mf * 16 + g;
            float2 v0 = make_float2(acc[mf][nf][0] + bv.x, acc[mf][nf][1] + bv.y);
            float2 v1 = make_float2(acc[mf][nf][2] + bv.x, acc[mf][nf][3] + bv.y);
            if (res) {
                float2 r0 = *(const float2*)(res + (size_t)row * 512 + col);
                float2 r1 = *(const float2*)(res + (size_t)(row + 8) * 512 + col);
                v0.x += r0.x; v0.y += r0.y; v1.x += r1.x; v1.y += r1.y;
            }
            *(float2*)(C + (size_t)row * 512 + col) = v0;
            *(float2*)(C + (size_t)(row + 8) * 512 + col) = v1;
        }
    }
}

struct GemmSet {
    const float* W[3];
    const float* b[3];
    const float* r[3];
    float*       C[3];
};

template<bool TRANSW>
__global__ void __launch_bounds__(128, 4) gemm_tc_kernel(const float* __restrict__ A, GemmSet s) {
    int z = blockIdx.z;
    gemm_tc_core<TRANSW>(A, s.W[z], s.b[z], s.r[z], s.C[z]);
}

// ---------------- attention core: one block per (b, h), 256 threads ---------
__global__ void __launch_bounds__(256) attn_kernel(
    const float* __restrict__ Q, const float* __restrict__ Kp,
    const float* __restrict__ Vp, float* __restrict__ O, int S)
{
    __shared__ float qs[25 * 64];
    __shared__ float kv[96 * 64];
    __shared__ float sc[25 * 96];
    int b = blockIdx.x >> 3, h = blockIdx.x & 7;
    int tid = threadIdx.x;
    const float scale = 0.125f;
    size_t qbase = (size_t)b * 25 * 512 + h * 64;
    size_t kbase = (size_t)b * S  * 512 + h * 64;

    for (int i = tid; i < 25 * 64; i += 256) qs[i] = Q[qbase + (size_t)(i >> 6) * 512 + (i & 63)];
    for (int i = tid; i < S  * 64; i += 256) kv[i] = Kp[kbase + (size_t)(i >> 6) * 512 + (i & 63)];
    __syncthreads();

    for (int i = tid; i < 25 * S; i += 256) {
        int l = i / S, s = i - l * S;
        float acc = 0.f;
        #pragma unroll 16
        for (int e = 0; e < 64; e++) acc += qs[l * 64 + e] * kv[s * 64 + e];
        sc[i] = acc * scale;
    }
    __syncthreads();

    int warp = tid >> 5, lane = tid & 31;
    for (int l = warp; l < 25; l += 8) {
        float mx = -1e30f;
        for (int s = lane; s < S; s += 32) mx = fmaxf(mx, sc[l * S + s]);
        #pragma unroll
        for (int o = 16; o; o >>= 1) mx = fmaxf(mx, __shfl_xor_sync(~0u, mx, o));
        float sum = 0.f;
        for (int s = lane; s < S; s += 32) {
            float e = __expf(sc[l * S + s] - mx);
            sc[l * S + s] = e; sum += e;
        }
        #pragma unroll
        for (int o = 16; o; o >>= 1) sum += __shfl_xor_sync(~0u, sum, o);
        float inv = __fdividef(1.f, sum);
        for (int s = lane; s < S; s += 32) sc[l * S + s] *= inv;
    }
    __syncthreads();

    for (int i = tid; i < S * 64; i += 256) kv[i] = Vp[kbase + (size_t)(i >> 6) * 512 + (i & 63)];
    __syncthreads();

    for (int i = tid; i < 25 * 64; i += 256) {
        int l = i >> 6, e = i & 63;
        float acc = 0.f;
        for (int s = 0; s < S; s++) acc += sc[l * S + s] * kv[s * 64 + e];
        O[qbase + (size_t)l * 512 + e] = acc;
    }
}

// ---------------- LayerNorm over rows of 512 (warp per row) ------------------
__global__ void __launch_bounds__(256) ln_kernel(
    const float* __restrict__ in, const float* __restrict__ g,
    const float* __restrict__ bb, float* __restrict__ out, int M)
{
    int row = blockIdx.x * 8 + (threadIdx.x >> 5);
    int lane = threadIdx.x & 31;
    if (row >= M) return;
    const float* p = in + (size_t)row * 512;
    float v[16];
    float s = 0.f, s2 = 0.f;
    #pragma unroll
    for (int i = 0; i < 16; i++) {
        v[i] = p[lane + 32 * i];
        s += v[i]; s2 += v[i] * v[i];
    }
    #pragma unroll
    for (int o = 16; o; o >>= 1) {
        s  += __shfl_xor_sync(~0u, s,  o);
        s2 += __shfl_xor_sync(~0u, s2, o);
    }
    float mean = s * (1.f / 512.f);
    float var  = s2 * (1.f / 512.f) - mean * mean;
    float rstd = rsqrtf(var + 1e-5f);
    float* q = out + (size_t)row * 512;
    #pragma unroll
    for (int i = 0; i < 16; i++) {
        int d = lane + 32 * i;
        q[d] = (v[i] - mean) * rstd * g[d] + bb[d];
    }
}

// ---------------- tiled transposes -------------------------------------------
__global__ void transpose_in_kernel(const float* __restrict__ in, float* __restrict__ out) {
    __shared__ float tile[32][33];
    int tx = threadIdx.x, ty = threadIdx.y;
    int t0 = blockIdx.x * 32, b0 = blockIdx.y * 32, k = blockIdx.z;
    #pragma unroll
    for (int i = 0; i < 4; i++)
        tile[ty + 8 * i][tx] = in[(size_t)(b0 + ty + 8 * i) * 12800 + k * 512 + t0 + tx];
    __syncthreads();
    #pragma unroll
    for (int i = 0; i < 4; i++)
        out[(size_t)(t0 + ty + 8 * i) * 3200 + k * 128 + b0 + tx] = tile[tx][ty + 8 * i];
}
__global__ void transpose_out_kernel(const float* __restrict__ in, float* __restrict__ out) {
    __shared__ float tile[32][33];
    int tx = threadIdx.x, ty = threadIdx.y;
    int c0 = blockIdx.x * 32, b0 = blockIdx.y * 32, l = blockIdx.z;
    #pragma unroll
    for (int i = 0; i < 4; i++)
        tile[ty + 8 * i][tx] = in[(size_t)(c0 + ty + 8 * i) * 3200 + l * 128 + b0 + tx];
    __syncthreads();
    #pragma unroll
    for (int i = 0; i < 4; i++)
        out[(size_t)((b0 + ty + 8 * i) * 25 + l) * 512 + c0 + tx] = tile[tx][ty + 8 * i];
}

__global__ void zero_flags_kernel() {
    int i = blockIdx.x * 256 + threadIdx.x;
    if (i < 33 * 4 * 32) g_flags[i] = 0;
}

DEVF void spinwait(const int* p, int need) {
    int v;
    do {
        asm volatile("ld.acquire.gpu.global.b32 %0, [%1];" : "=r"(v) : "l"(p) : "memory");
    } while (v < need);
}

// ---------------- tensor-core LSTM wavefront ---------------------------------
// 128 blocks = 32 layers x 4 chunks(32 batches). 160 threads:
// warps 0-3 compute (warp w owns units 8w..8w+7 via 2 m16 tiles: {i,f} and {g,o}),
// warp 4 = IO (flag wait + x prefetch into B). B = [x(25); h(25); pad] tf32 in smem,
// double-buffered, stride 40 => conflict-free mma fragment loads. c stays fp32 regs.
#define BROWS 56
#define BSTR  40
__global__ void __launch_bounds__(160, 1) lstm_wave_kernel(
    const float* __restrict__ Wih, const float* __restrict__ Whh,
    const float* __restrict__ bih, const float* __restrict__ bhh)
{
    __shared__ __align__(16) unsigned Bsm[2][BROWS][BSTR];

    int layer = blockIdx.x & 31;
    int chunk = blockIdx.x >> 5;
    int b0 = chunk * 32;
    const float* in  = g_Y + (size_t)layer * YSTRIDE;
    float* outp      = g_Y + (size_t)(layer + 1) * YSTRIDE;
    const int* inflag = g_flags + (layer * 4 + chunk) * 32;
    int* outflag      = g_flags + ((layer + 1) * 4 + chunk) * 32;

    int tid = threadIdx.x;
    int warp = tid >> 5, lane = tid & 31;
    int g = lane >> 2, tg = lane & 3;

    // zero both B buffers (pad rows must be finite; h rows start at 0)
    for (int i = tid; i < 2 * BROWS * BSTR; i += 160) ((unsigned*)Bsm)[i] = 0;

    // ---- compute-warp setup: preload A fragments (weights, tf32) + biases ----
    unsigned afr[2][7][4];
    float bias_i = 0.f, bias_f = 0.f, bias_g = 0.f, bias_o = 0.f;
    int u = warp * 8 + g;
    bool isComp = (warp < 4);
    bool valid = isComp && (u < 25);
    if (isComp) {
        const float* WI = Wih + (size_t)layer * 2500;
        const float* WH = Whh + (size_t)layer * 2500;
        #pragma unroll
        for (int T = 0; T < 2; T++) {
            int rowA = (T == 0 ? 0 : 50) + u;    // i / g gate rows
            int rowB = (T == 0 ? 25 : 75) + u;   // f / o gate rows
            #pragma unroll
            for (int ks = 0; ks < 7; ks++) {
                #pragma unroll
                for (int q = 0; q < 4; q++) {
                    int k = ks * 8 + tg + (q >= 2 ? 4 : 0);
                    int row = (q & 1) ? rowB : rowA;
                    float w = 0.f;
                    if (valid) {
                        if (k < 25)      w = WI[row * 25 + k];
                        else if (k < 50) w = WH[row * 25 + (k - 25)];
                    }
                    afr[T][ks][q] = totf(w);
                }
            }
        }
        if (valid) {
            bias_i = bih[layer * 100 + u]      + bhh[layer * 100 + u];
            bias_f = bih[layer * 100 + 25 + u] + bhh[layer * 100 + 25 + u];
            bias_g = bih[layer * 100 + 50 + u] + bhh[layer * 100 + 50 + u];
            bias_o = bih[layer * 100 + 75 + u] + bhh[layer * 100 + 75 + u];
        }
    }
    float c[8];
    #pragma unroll
    for (int i = 0; i < 8; i++) c[i] = 0.f;
    __syncthreads();

    // prologue: x_0 -> B[0] rows 0..24
    if (warp == 4) {
        if (layer > 0 && lane == 0) spinwait(inflag, 1);
        __syncwarp();
        #pragma unroll
        for (int k = 0; k < 25; k++)
            Bsm[0][k][lane] = totf(in[k * 128 + b0 + lane]);
    }
    __syncthreads();

    for (int t = 0; t < 512; t++) {
        int par = t & 1;
        if (isComp) {
            float acc0[4][4], acc1[4][4];
            #pragma unroll
            for (int nf = 0; nf < 4; nf++) {
                acc0[nf][0] = bias_i; acc0[nf][1] = bias_i;
                acc0[nf][2] = bias_f; acc0[nf][3] = bias_f;
                acc1[nf][0] = bias_g; acc1[nf][1] = bias_g;
                acc1[nf][2] = bias_o; acc1[nf][3] = bias_o;
            }
            const unsigned* Bp = &Bsm[par][0][0];
            #pragma unroll
            for (int ks = 0; ks < 7; ks++) {
                int r0 = (ks * 8 + tg) * BSTR;
                #pragma unroll
                for (int nf = 0; nf < 4; nf++) {
                    unsigned b0v = Bp[r0 + nf * 8 + g];
                    unsigned b1v = Bp[r0 + 4 * BSTR + nf * 8 + g];
                    mma_tf32(acc0[nf], afr[0][ks], b0v, b1v);
                    mma_tf32(acc1[nf], afr[1][ks], b0v, b1v);
                }
            }
            unsigned* Bn = &Bsm[par ^ 1][0][0];
            #pragma unroll
            for (int nf = 0; nf < 4; nf++) {
                float i0 = sig_fast(acc0[nf][0]),  i1 = sig_fast(acc0[nf][1]);
                float f0 = sig_fast(acc0[nf][2]),  f1 = sig_fast(acc0[nf][3]);
                float q0 = tanh_fast(acc1[nf][0]), q1 = tanh_fast(acc1[nf][1]);
                float o0 = sig_fast(acc1[nf][2]),  o1 = sig_fast(acc1[nf][3]);
                c[2 * nf]     = f0 * c[2 * nf]     + i0 * q0;
                c[2 * nf + 1] = f1 * c[2 * nf + 1] + i1 * q1;
                float h0 = o0 * tanh_fast(c[2 * nf]);
                float h1 = o1 * tanh_fast(c[2 * nf + 1]);
                if (valid) {
                    uint2 hp = make_uint2(totf(h0), totf(h1));
                    *(uint2*)&Bn[(25 + u) * BSTR + nf * 8 + 2 * tg] = hp;
                    *(float2*)(outp + (size_t)t * 3200 + u * 128 + b0 + nf * 8 + 2 * tg)
                        = make_float2(h0, h1);
                }
            }
        } else {
            if (t < 511) {
                if (layer > 0 && lane == 0) spinwait(inflag, t + 2);
                __syncwarp();
                const float* src = in + (size_t)(t + 1) * 3200 + b0;
                #pragma unroll
                for (int k = 0; k < 25; k++)
                    Bsm[par ^ 1][k][lane] = totf(src[k * 128 + lane]);
            }
        }
        __syncthreads();
        if (tid == 0) {
            int nv = t + 1;
            asm volatile("st.release.gpu.global.b32 [%0], %1;" :: "l"(outflag), "r"(nv) : "memory");
        }
    }
}

// ---------------- launcher ---------------------------------------------------
extern "C" void kernel_launch(void* const* d_in, const int* in_sizes, int n_in,
                              void* d_out, int out_size)
{
    const float* x     = (const float*)d_in[0];
    const float* cross = (const float*)d_in[1];
    const float* Wq_s = (const float*)d_in[2];  const float* bq_s = (const float*)d_in[3];
    const float* Wk_s = (const float*)d_in[4];  const float* bk_s = (const float*)d_in[5];
    const float* Wv_s = (const float*)d_in[6];  const float* bv_s = (const float*)d_in[7];
    const float* Wo_s = (const float*)d_in[8];  const float* bo_s = (const float*)d_in[9];
    const float* Wq_c = (const float*)d_in[10]; const float* bq_c = (const float*)d_in[11];
    const float* Wk_c = (const float*)d_in[12]; const float* bk_c = (const float*)d_in[13];
    const float* Wv_c = (const float*)d_in[14]; const float* bv_c = (const float*)d_in[15];
    const float* Wo_c = (const float*)d_in[16]; const float* bo_c = (const float*)d_in[17];
    const float* g1 = (const float*)d_in[18]; const float* b1 = (const float*)d_in[19];
    const float* g2 = (const float*)d_in[20]; const float* b2 = (const float*)d_in[21];
    const float* g3 = (const float*)d_in[22]; const float* b3 = (const float*)d_in[23];
    const float* W_ih = (const float*)d_in[24];
    const float* W_hh = (const float*)d_in[25];
    const float* b_ih = (const float*)d_in[26];
    const float* b_hh = (const float*)d_in[27];
    const float* Wc = (const float*)d_in[28]; const float* bc = (const float*)d_in[29];
    float* out = (float*)d_out;

    float *gq, *gk, *gv, *gctx, *gx1, *gx2, *gtmp, *gyt, *gY;
    cudaGetSymbolAddress((void**)&gq,   g_q);
    cudaGetSymbolAddress((void**)&gk,   g_k);
    cudaGetSymbolAddress((void**)&gv,   g_v);
    cudaGetSymbolAddress((void**)&gctx, g_ctx);
    cudaGetSymbolAddress((void**)&gx1,  g_x1);
    cudaGetSymbolAddress((void**)&gx2,  g_x2);
    cudaGetSymbolAddress((void**)&gtmp, g_tmp);
    cudaGetSymbolAddress((void**)&gyt,  g_yt);
    cudaGetSymbolAddress((void**)&gY,   g_Y);

    const int M1 = 3200;    // B*L
    zero_flags_kernel<<<17, 256>>>();

    // ---- self attention ----
    {
        GemmSet s = {{Wq_s, Wk_s, Wv_s}, {bq_s, bk_s, bv_s},
                     {nullptr, nullptr, nullptr}, {gq, gk, gv}};
        gemm_tc_kernel<false><<<dim3(50, 8, 3), 128>>>(x, s);
    }
    attn_kernel<<<128 * 8, 256>>>(gq, gk, gv, gctx, 25);
    {
        GemmSet s = {{Wo_s, nullptr, nullptr}, {bo_s, nullptr, nullptr},
                     {x, nullptr, nullptr}, {gtmp, nullptr, nullptr}};
        gemm_tc_kernel<false><<<dim3(50, 8, 1), 128>>>(gctx, s);
    }
    ln_kernel<<<M1 / 8, 256>>>(gtmp, g1, b1, gx1, M1);

    // ---- cross attention ----
    {
        GemmSet s = {{Wq_c, nullptr, nullptr}, {bq_c, nullptr, nullptr},
                     {nullptr, nullptr, nullptr}, {gq, nullptr, nullptr}};
        gemm_tc_kernel<false><<<dim3(50, 8, 1), 128>>>(gx1, s);
    }
    {
        GemmSet s = {{Wk_c, Wv_c, nullptr}, {bk_c, bv_c, nullptr},
                     {nullptr, nullptr, nullptr}, {gk, gv, nullptr}};
        gemm_tc_kernel<false><<<dim3(192, 8, 2), 128>>>(cross, s);
    }
    attn_kernel<<<128 * 8, 256>>>(gq, gk, gv, gctx, 96);
    {
        GemmSet s = {{Wo_c, nullptr, nullptr}, {bo_c, nullptr, nullptr},
                     {gx1, nullptr, nullptr}, {gtmp, nullptr, nullptr}};
        gemm_tc_kernel<false><<<dim3(50, 8, 1), 128>>>(gctx, s);
    }
    ln_kernel<<<M1 / 8, 256>>>(gtmp, g2, b2, gx2, M1);

    // ---- LSTM wavefront over feature axis ----
    transpose_in_kernel<<<dim3(16, 4, 25), dim3(32, 8)>>>(gx2, gY);
    lstm_wave_kernel<<<128, 160>>>(W_ih, W_hh, b_ih, b_hh);

    // ---- pointwise conv + residual + final LN ----
    transpose_out_kernel<<<dim3(16, 4, 25), dim3(32, 8)>>>(gY + 32ull * YSTRIDE, gyt);
    {
        GemmSet s = {{Wc, nullptr, nullptr}, {bc, nullptr, nullptr},
                     {gx2, nullptr, nullptr}, {gtmp, nullptr, nullptr}};
        gemm_tc_kernel<true><<<dim3(50, 8, 1), 128>>>(gyt, s);
    }
    ln_kernel<<<M1 / 8, 256>>>(gtmp, g3, b3, out, M1);
}

// round 10
// speedup vs baseline: 2.9108x; 1.0848x over previous
#include <cuda_runtime.h>
#include <cstddef>

#define DEVF __device__ __forceinline__
typedef unsigned long long ull;

// ---------------- scratch (device globals; no allocations allowed) ----------
__device__ float g_q  [3200 * 512];
__device__ float g_k  [12288 * 512];
__device__ float g_v  [12288 * 512];
__device__ float g_ctx[3200 * 512];
__device__ float g_x1 [3200 * 512];
__device__ float g_x2 [3200 * 512];
__device__ float g_tmp[3200 * 512];
__device__ float g_yt [3200 * 512];

// LSTM wavefront buffers: Y[l][t][k][b], l = 0..32, t<512, k<25, b<128
#define YSTRIDE 1638400   // 512*25*128
__device__ float g_Y[33ull * YSTRIDE];
__device__ int   g_flags[33 * 4 * 32];   // (layer,chunk) progress, 128B padded

// ---------------- activations ------------------------------------------------
DEVF float tanh_fast(float x) {
    float y; asm("tanh.approx.f32 %0, %1;" : "=f"(y) : "f"(x)); return y;
}
DEVF float sig_fast(float x) { return fmaf(tanh_fast(0.5f * x), 0.5f, 0.5f); }

// ---------------- tf32 helpers -----------------------------------------------
DEVF unsigned totf(float x) {
    unsigned r; asm("cvt.rna.tf32.f32 %0, %1;" : "=r"(r) : "f"(x)); return r;
}
DEVF void mma_tf32(float* c, const unsigned* a, unsigned b0, unsigned b1) {
    asm("mma.sync.aligned.m16n8k8.row.col.f32.tf32.tf32.f32 "
        "{%0,%1,%2,%3}, {%4,%5,%6,%7}, {%8,%9}, {%0,%1,%2,%3};"
        : "+f"(c[0]), "+f"(c[1]), "+f"(c[2]), "+f"(c[3])
        : "r"(a[0]), "r"(a[1]), "r"(a[2]), "r"(a[3]), "r"(b0), "r"(b1));
}

DEVF void cpasync16(unsigned dst, const void* src) {
    asm volatile("cp.async.cg.shared.global [%0], [%1], 16;" :: "r"(dst), "l"(src));
}
DEVF void cp_commit() { asm volatile("cp.async.commit_group;"); }
DEVF void cp_wait2()  { asm volatile("cp.async.wait_group 2;"); }

// ---------------- tf32 tensor-core GEMM, cp.async 4-stage, BK=16 -------------
// C[.,512] = A[.,512] @ W (+bias)(+res). TRANSW: W stored [N,K] else [K,N].
// Tile 64x64, 128 threads = 2x2 warps (warp 32x32). Raw fp32 into mma (tf32 trunc).
#define ASTR 20
#define AWRD (64 * ASTR)       // 1280
#define BWRD 1296              // >= max(16*72, 64*20)
template<bool TRANSW>
DEVF void gemm_tc_core(const float* __restrict__ A, const float* __restrict__ W,
                       const float* __restrict__ bias, const float* __restrict__ res,
                       float* __restrict__ C)
{
    __shared__ __align__(16) float As[4][AWRD];
    __shared__ __align__(16) float Bsm[4][BWRD];

    int tid = threadIdx.x;
    int bm = blockIdx.x * 64, bn = blockIdx.y * 64;
    int lane = tid & 31, wid = tid >> 5;
    int wm = wid & 1, wn = wid >> 1;
    int g = lane >> 2, tg = lane & 3;

    float acc[2][4][4];
    #pragma unroll
    for (int i = 0; i < 2; i++)
        #pragma unroll
        for (int j = 0; j < 4; j++)
            #pragma unroll
            for (int q = 0; q < 4; q++) acc[i][j][q] = 0.f;

    int ar = tid >> 1, ac = (tid & 1) * 8;
    const float* Asrc = A + (size_t)(bm + ar) * 512 + ac;
    int kk = tid >> 3, nn = (tid & 7) * 8;       // !TRANSW: B row k, col group
    int nr = tid >> 1, kc = (tid & 1) * 8;       // TRANSW: B row n, k group
    const float* Bsrc = TRANSW ? (W + (size_t)(bn + nr) * 512 + kc)
                               : (W + (size_t)kk * 512 + bn + nn);

    unsigned asb = (unsigned)__cvta_generic_to_shared(&As[0][0]);
    unsigned bsb = (unsigned)__cvta_generic_to_shared(&Bsm[0][0]);
    unsigned adst = asb + (ar * ASTR + ac) * 4;
    unsigned bdst = bsb + (TRANSW ? (nr * ASTR + kc) : (kk * 72 + nn)) * 4;

    #pragma unroll
    for (int p = 0; p < 3; p++) {
        int k0 = p * 16;
        cpasync16(adst + p * AWRD * 4, Asrc + k0);
        cpasync16(adst + p * AWRD * 4 + 16, Asrc + k0 + 4);
        const float* bs = TRANSW ? (Bsrc + k0) : (Bsrc + (size_t)k0 * 512);
        cpasync16(bdst + p * BWRD * 4, bs);
        cpasync16(bdst + p * BWRD * 4 + 16, bs + 4);
        cp_commit();
    }

    int am0 = wm * 32 + g;
    int cn0 = wn * 32 + g;

    for (int it = 0; it < 32; it++) {
        int st = it & 3;
        cp_wait2();
        __syncthreads();
        if (it + 3 < 32) {
            int tl = it + 3, ns = tl & 3;
            int k0 = tl * 16;
            cpasync16(adst + ns * AWRD * 4, Asrc + k0);
            cpasync16(adst + ns * AWRD * 4 + 16, Asrc + k0 + 4);
            const float* bs = TRANSW ? (Bsrc + k0) : (Bsrc + (size_t)k0 * 512);
            cpasync16(bdst + ns * BWRD * 4, bs);
            cpasync16(bdst + ns * BWRD * 4 + 16, bs + 4);
        }
        cp_commit();

        const unsigned* Au = (const unsigned*)As[st];
        const unsigned* Bu = (const unsigned*)Bsm[st];
        #pragma unroll
        for (int ks = 0; ks < 2; ks++) {
            int klo = ks * 8 + tg;
            unsigned afr[2][4];
            #pragma unroll
            for (int mf = 0; mf < 2; mf++) {
                int m = am0 + mf * 16;
                afr[mf][0] = Au[m * ASTR + klo];
                afr[mf][1] = Au[(m + 8) * ASTR + klo];
                afr[mf][2] = Au[m * ASTR + klo + 4];
                afr[mf][3] = Au[(m + 8) * ASTR + klo + 4];
            }
            #pragma unroll
            for (int nf = 0; nf < 4; nf++) {
                int col = wn * 32 + nf * 8 + g;
                unsigned b0, b1;
                if (!TRANSW) {
                    b0 = Bu[klo * 72 + col];
                    b1 = Bu[(klo + 4) * 72 + col];
                } else {
                    b0 = Bu[col * ASTR + klo];
                    b1 = Bu[col * ASTR + klo + 4];
                }
                mma_tf32(acc[0][nf], afr[0], b0, b1);
                mma_tf32(acc[1][nf], afr[1], b0, b1);
            }
        }
        __syncthreads();
    }

    // ---- epilogue ----
    #pragma unroll
    for (int nf = 0; nf < 4; nf++) {
        int col = bn + wn * 32 + nf * 8 + 2 * tg;
        float2 bv = *(const float2*)(bias + col);
        #pragma unroll
        for (int mf = 0; mf < 2; mf++) {
            int row = bm + wm * 32 + mf * 16 + g;
            float2 v0 = make_float2(acc[mf][nf][0] + bv.x, acc[mf][nf][1] + bv.y);
            float2 v1 = make_float2(acc[mf][nf][2] + bv.x, acc[mf][nf][3] + bv.y);
            if (res) {
                float2 r0 = *(const float2*)(res + (size_t)row * 512 + col);
                float2 r1 = *(const float2*)(res + (size_t)(row + 8) * 512 + col);
                v0.x += r0.x; v0.y += r0.y; v1.x += r1.x; v1.y += r1.y;
            }
            *(float2*)(C + (size_t)row * 512 + col) = v0;
            *(float2*)(C + (size_t)(row + 8) * 512 + col) = v1;
        }
    }
}

struct GemmSet {
    const float* W[3];
    const float* b[3];
    const float* r[3];
    float*       C[3];
};

template<bool TRANSW>
__global__ void __launch_bounds__(128, 5) gemm_tc_kernel(const float* __restrict__ A, GemmSet s) {
    int z = blockIdx.z;
    gemm_tc_core<TRANSW>(A, s.W[z], s.b[z], s.r[z], s.C[z]);
}

// ---------------- attention core: one block per (b, h), 256 threads ---------
template<int S>
__global__ void __launch_bounds__(256) attn_kernel(
    const float* __restrict__ Q, const float* __restrict__ Kp,
    const float* __restrict__ Vp, float* __restrict__ O)
{
    __shared__ float qs[25 * 64];
    __shared__ __align__(16) float kv[96 * 64];
    __shared__ float sc[25 * S];
    int b = blockIdx.x >> 3, h = blockIdx.x & 7;
    int tid = threadIdx.x;
    const float scale = 0.125f;
    size_t qbase = (size_t)b * 25 * 512 + h * 64;
    size_t kbase = (size_t)b * S  * 512 + h * 64;

    for (int i = tid; i < 25 * 64; i += 256) qs[i] = Q[qbase + (size_t)(i >> 6) * 512 + (i & 63)];
    for (int i = tid; i < S  * 64; i += 256) kv[i] = Kp[kbase + (size_t)(i >> 6) * 512 + (i & 63)];
    __syncthreads();

    for (int i = tid; i < 25 * S; i += 256) {
        int l = i / S, s = i - l * S;
        float acc = 0.f;
        #pragma unroll
        for (int e4 = 0; e4 < 16; e4++) {
            float4 q4 = *(const float4*)&qs[l * 64 + e4 * 4];
            float4 k4 = *(const float4*)&kv[s * 64 + e4 * 4];
            acc += q4.x * k4.x + q4.y * k4.y + q4.z * k4.z + q4.w * k4.w;
        }
        sc[i] = acc * scale;
    }
    __syncthreads();

    int warp = tid >> 5, lane = tid & 31;
    for (int l = warp; l < 25; l += 8) {
        float mx = -1e30f;
        for (int s = lane; s < S; s += 32) mx = fmaxf(mx, sc[l * S + s]);
        #pragma unroll
        for (int o = 16; o; o >>= 1) mx = fmaxf(mx, __shfl_xor_sync(~0u, mx, o));
        float sum = 0.f;
        for (int s = lane; s < S; s += 32) {
            float e = __expf(sc[l * S + s] - mx);
            sc[l * S + s] = e; sum += e;
        }
        #pragma unroll
        for (int o = 16; o; o >>= 1) sum += __shfl_xor_sync(~0u, sum, o);
        float inv = __fdividef(1.f, sum);
        for (int s = lane; s < S; s += 32) sc[l * S + s] *= inv;
    }
    __syncthreads();

    for (int i = tid; i < S * 64; i += 256) kv[i] = Vp[kbase + (size_t)(i >> 6) * 512 + (i & 63)];
    __syncthreads();

    // V multiply: thread -> (l, 4 consecutive e)
    for (int i = tid; i < 25 * 16; i += 256) {
        int l = i >> 4, e4 = (i & 15) * 4;
        float4 acc = make_float4(0.f, 0.f, 0.f, 0.f);
        const float* scl = &sc[l * S];
        #pragma unroll 4
        for (int s = 0; s < S; s++) {
            float w = scl[s];
            float4 v4 = *(const float4*)&kv[s * 64 + e4];
            acc.x += w * v4.x; acc.y += w * v4.y;
            acc.z += w * v4.z; acc.w += w * v4.w;
        }
        *(float4*)(&O[qbase + (size_t)l * 512 + e4]) = acc;
    }
}

// ---------------- LayerNorm over rows of 512 (warp per row) ------------------
__global__ void __launch_bounds__(256) ln_kernel(
    const float* __restrict__ in, const float* __restrict__ g,
    const float* __restrict__ bb, float* __restrict__ out, int M)
{
    int row = blockIdx.x * 8 + (threadIdx.x >> 5);
    int lane = threadIdx.x & 31;
    if (row >= M) return;
    const float* p = in + (size_t)row * 512;
    float v[16];
    float s = 0.f, s2 = 0.f;
    #pragma unroll
    for (int i = 0; i < 16; i++) {
        v[i] = p[lane + 32 * i];
        s += v[i]; s2 += v[i] * v[i];
    }
    #pragma unroll
    for (int o = 16; o; o >>= 1) {
        s  += __shfl_xor_sync(~0u, s,  o);
        s2 += __shfl_xor_sync(~0u, s2, o);
    }
    float mean = s * (1.f / 512.f);
    float var  = s2 * (1.f / 512.f) - mean * mean;
    float rstd = rsqrtf(var + 1e-5f);
    float* q = out + (size_t)row * 512;
    #pragma unroll
    for (int i = 0; i < 16; i++) {
        int d = lane + 32 * i;
        q[d] = (v[i] - mean) * rstd * g[d] + bb[d];
    }
}

// ---------------- tiled transposes -------------------------------------------
__global__ void transpose_in_kernel(const float* __restrict__ in, float* __restrict__ out) {
    __shared__ float tile[32][33];
    int tx = threadIdx.x, ty = threadIdx.y;
    int t0 = blockIdx.x * 32, b0 = blockIdx.y * 32, k = blockIdx.z;
    #pragma unroll
    for (int i = 0; i < 4; i++)
        tile[ty + 8 * i][tx] = in[(size_t)(b0 + ty + 8 * i) * 12800 + k * 512 + t0 + tx];
    __syncthreads();
    #pragma unroll
    for (int i = 0; i < 4; i++)
        out[(size_t)(t0 + ty + 8 * i) * 3200 + k * 128 + b0 + tx] = tile[tx][ty + 8 * i];
}
__global__ void transpose_out_kernel(const float* __restrict__ in, float* __restrict__ out) {
    __shared__ float tile[32][33];
    int tx = threadIdx.x, ty = threadIdx.y;
    int c0 = blockIdx.x * 32, b0 = blockIdx.y * 32, l = blockIdx.z;
    #pragma unroll
    for (int i = 0; i < 4; i++)
        tile[ty + 8 * i][tx] = in[(size_t)(c0 + ty + 8 * i) * 3200 + l * 128 + b0 + tx];
    __syncthreads();
    #pragma unroll
    for (int i = 0; i < 4; i++)
        out[(size_t)((b0 + ty + 8 * i) * 25 + l) * 512 + c0 + tx] = tile[tx][ty + 8 * i];
}

__global__ void zero_flags_kernel() {
    int i = blockIdx.x * 256 + threadIdx.x;
    if (i < 33 * 4 * 32) g_flags[i] = 0;
}

DEVF void spinwait(const int* p, int need) {
    int v;
    do {
        asm volatile("ld.acquire.gpu.global.b32 %0, [%1];" : "=r"(v) : "l"(p) : "memory");
    } while (v < need);
}

// ---------------- tensor-core LSTM wavefront (unchanged from R9) -------------
#define BROWS 56
#define BSTR  40
__global__ void __launch_bounds__(160, 1) lstm_wave_kernel(
    const float* __restrict__ Wih, const float* __restrict__ Whh,
    const float* __restrict__ bih, const float* __restrict__ bhh)
{
    __shared__ __align__(16) unsigned Bsm[2][BROWS][BSTR];

    int layer = blockIdx.x & 31;
    int chunk = blockIdx.x >> 5;
    int b0 = chunk * 32;
    const float* in  = g_Y + (size_t)layer * YSTRIDE;
    float* outp      = g_Y + (size_t)(layer + 1) * YSTRIDE;
    const int* inflag = g_flags + (layer * 4 + chunk) * 32;
    int* outflag      = g_flags + ((layer + 1) * 4 + chunk) * 32;

    int tid = threadIdx.x;
    int warp = tid >> 5, lane = tid & 31;
    int g = lane >> 2, tg = lane & 3;

    for (int i = tid; i < 2 * BROWS * BSTR; i += 160) ((unsigned*)Bsm)[i] = 0;

    unsigned afr[2][7][4];
    float bias_i = 0.f, bias_f = 0.f, bias_g = 0.f, bias_o = 0.f;
    int u = warp * 8 + g;
    bool isComp = (warp < 4);
    bool valid = isComp && (u < 25);
    if (isComp) {
        const float* WI = Wih + (size_t)layer * 2500;
        const float* WH = Whh + (size_t)layer * 2500;
        #pragma unroll
        for (int T = 0; T < 2; T++) {
            int rowA = (T == 0 ? 0 : 50) + u;
            int rowB = (T == 0 ? 25 : 75) + u;
            #pragma unroll
            for (int ks = 0; ks < 7; ks++) {
                #pragma unroll
                for (int q = 0; q < 4; q++) {
                    int k = ks * 8 + tg + (q >= 2 ? 4 : 0);
                    int row = (q & 1) ? rowB : rowA;
                    float w = 0.f;
                    if (valid) {
                        if (k < 25)      w = WI[row * 25 + k];
                        else if (k < 50) w = WH[row * 25 + (k - 25)];
                    }
                    afr[T][ks][q] = totf(w);
                }
            }
        }
        if (valid) {
            bias_i = bih[layer * 100 + u]      + bhh[layer * 100 + u];
            bias_f = bih[layer * 100 + 25 + u] + bhh[layer * 100 + 25 + u];
            bias_g = bih[layer * 100 + 50 + u] + bhh[layer * 100 + 50 + u];
            bias_o = bih[layer * 100 + 75 + u] + bhh[layer * 100 + 75 + u];
        }
    }
    float c[8];
    #pragma unroll
    for (int i = 0; i < 8; i++) c[i] = 0.f;
    __syncthreads();

    if (warp == 4) {
        if (layer > 0 && lane == 0) spinwait(inflag, 1);
        __syncwarp();
        #pragma unroll
        for (int k = 0; k < 25; k++)
            Bsm[0][k][lane] = totf(in[k * 128 + b0 + lane]);
    }
    __syncthreads();

    for (int t = 0; t < 512; t++) {
        int par = t & 1;
        if (isComp) {
            float acc0[4][4], acc1[4][4];
            #pragma unroll
            for (int nf = 0; nf < 4; nf++) {
                acc0[nf][0] = bias_i; acc0[nf][1] = bias_i;
                acc0[nf][2] = bias_f; acc0[nf][3] = bias_f;
                acc1[nf][0] = bias_g; acc1[nf][1] = bias_g;
                acc1[nf][2] = bias_o; acc1[nf][3] = bias_o;
            }
            const unsigned* Bp = &Bsm[par][0][0];
            #pragma unroll
            for (int ks = 0; ks < 7; ks++) {
                int r0 = (ks * 8 + tg) * BSTR;
                #pragma unroll
                for (int nf = 0; nf < 4; nf++) {
                    unsigned b0v = Bp[r0 + nf * 8 + g];
                    unsigned b1v = Bp[r0 + 4 * BSTR + nf * 8 + g];
                    mma_tf32(acc0[nf], afr[0][ks], b0v, b1v);
                    mma_tf32(acc1[nf], afr[1][ks], b0v, b1v);
                }
            }
            unsigned* Bn = &Bsm[par ^ 1][0][0];
            #pragma unroll
            for (int nf = 0; nf < 4; nf++) {
                float i0 = sig_fast(acc0[nf][0]),  i1 = sig_fast(acc0[nf][1]);
                float f0 = sig_fast(acc0[nf][2]),  f1 = sig_fast(acc0[nf][3]);
                float q0 = tanh_fast(acc1[nf][0]), q1 = tanh_fast(acc1[nf][1]);
                float o0 = sig_fast(acc1[nf][2]),  o1 = sig_fast(acc1[nf][3]);
                c[2 * nf]     = f0 * c[2 * nf]     + i0 * q0;
                c[2 * nf + 1] = f1 * c[2 * nf + 1] + i1 * q1;
                float h0 = o0 * tanh_fast(c[2 * nf]);
                float h1 = o1 * tanh_fast(c[2 * nf + 1]);
                if (valid) {
                    uint2 hp = make_uint2(totf(h0), totf(h1));
                    *(uint2*)&Bn[(25 + u) * BSTR + nf * 8 + 2 * tg] = hp;
                    *(float2*)(outp + (size_t)t * 3200 + u * 128 + b0 + nf * 8 + 2 * tg)
                        = make_float2(h0, h1);
                }
            }
        } else {
            if (t < 511) {
                if (layer > 0 && lane == 0) spinwait(inflag, t + 2);
                __syncwarp();
                const float* src = in + (size_t)(t + 1) * 3200 + b0;
                #pragma unroll
                for (int k = 0; k < 25; k++)
                    Bsm[par ^ 1][k][lane] = totf(src[k * 128 + lane]);
            }
        }
        __syncthreads();
        if (tid == 0) {
            int nv = t + 1;
            asm volatile("st.release.gpu.global.b32 [%0], %1;" :: "l"(outflag), "r"(nv) : "memory");
        }
    }
}

// ---------------- launcher ---------------------------------------------------
extern "C" void kernel_launch(void* const* d_in, const int* in_sizes, int n_in,
                              void* d_out, int out_size)
{
    const float* x     = (const float*)d_in[0];
    const float* cross = (const float*)d_in[1];
    const float* Wq_s = (const float*)d_in[2];  const float* bq_s = (const float*)d_in[3];
    const float* Wk_s = (const float*)d_in[4];  const float* bk_s = (const float*)d_in[5];
    const float* Wv_s = (const float*)d_in[6];  const float* bv_s = (const float*)d_in[7];
    const float* Wo_s = (const float*)d_in[8];  const float* bo_s = (const float*)d_in[9];
    const float* Wq_c = (const float*)d_in[10]; const float* bq_c = (const float*)d_in[11];
    const float* Wk_c = (const float*)d_in[12]; const float* bk_c = (const float*)d_in[13];
    const float* Wv_c = (const float*)d_in[14]; const float* bv_c = (const float*)d_in[15];
    const float* Wo_c = (const float*)d_in[16]; const float* bo_c = (const float*)d_in[17];
    const float* g1 = (const float*)d_in[18]; const float* b1 = (const float*)d_in[19];
    const float* g2 = (const float*)d_in[20]; const float* b2 = (const float*)d_in[21];
    const float* g3 = (const float*)d_in[22]; const float* b3 = (const float*)d_in[23];
    const float* W_ih = (const float*)d_in[24];
    const float* W_hh = (const float*)d_in[25];
    const float* b_ih = (const float*)d_in[26];
    const float* b_hh = (const float*)d_in[27];
    const float* Wc = (const float*)d_in[28]; const float* bc = (const float*)d_in[29];
    float* out = (float*)d_out;

    float *gq, *gk, *gv, *gctx, *gx1, *gx2, *gtmp, *gyt, *gY;
    cudaGetSymbolAddress((void**)&gq,   g_q);
    cudaGetSymbolAddress((void**)&gk,   g_k);
    cudaGetSymbolAddress((void**)&gv,   g_v);
    cudaGetSymbolAddress((void**)&gctx, g_ctx);
    cudaGetSymbolAddress((void**)&gx1,  g_x1);
    cudaGetSymbolAddress((void**)&gx2,  g_x2);
    cudaGetSymbolAddress((void**)&gtmp, g_tmp);
    cudaGetSymbolAddress((void**)&gyt,  g_yt);
    cudaGetSymbolAddress((void**)&gY,   g_Y);

    const int M1 = 3200;    // B*L
    zero_flags_kernel<<<17, 256>>>();

    // ---- self attention ----
    {
        GemmSet s = {{Wq_s, Wk_s, Wv_s}, {bq_s, bk_s, bv_s},
                     {nullptr, nullptr, nullptr}, {gq, gk, gv}};
        gemm_tc_kernel<false><<<dim3(50, 8, 3), 128>>>(x, s);
    }
    attn_kernel<25><<<128 * 8, 256>>>(gq, gk, gv, gctx);
    {
        GemmSet s = {{Wo_s, nullptr, nullptr}, {bo_s, nullptr, nullptr},
                     {x, nullptr, nullptr}, {gtmp, nullptr, nullptr}};
        gemm_tc_kernel<false><<<dim3(50, 8, 1), 128>>>(gctx, s);
    }
    ln_kernel<<<M1 / 8, 256>>>(gtmp, g1, b1, gx1, M1);

    // ---- cross attention ----
    {
        GemmSet s = {{Wq_c, nullptr, nullptr}, {bq_c, nullptr, nullptr},
                     {nullptr, nullptr, nullptr}, {gq, nullptr, nullptr}};
        gemm_tc_kernel<false><<<dim3(50, 8, 1), 128>>>(gx1, s);
    }
    {
        GemmSet s = {{Wk_c, Wv_c, nullptr}, {bk_c, bv_c, nullptr},
                     {nullptr, nullptr, nullptr}, {gk, gv, nullptr}};
        gemm_tc_kernel<false><<<dim3(192, 8, 2), 128>>>(cross, s);
    }
    attn_kernel<96><<<128 * 8, 256>>>(gq, gk, gv, gctx);
    {
        GemmSet s = {{Wo_c, nullptr, nullptr}, {bo_c, nullptr, nullptr},
                     {gx1, nullptr, nullptr}, {gtmp, nullptr, nullptr}};
        gemm_tc_kernel<false><<<dim3(50, 8, 1), 128>>>(gctx, s);
    }
    ln_kernel<<<M1 / 8, 256>>>(gtmp, g2, b2, gx2, M1);

    // ---- LSTM wavefront over feature axis ----
    transpose_in_kernel<<<dim3(16, 4, 25), dim3(32, 8)>>>(gx2, gY);
    lstm_wave_kernel<<<128, 160>>>(W_ih, W_hh, b_ih, b_hh);

    // ---- pointwise conv + residual + final LN ----
    transpose_out_kernel<<<dim3(16, 4, 25), dim3(32, 8)>>>(gY + 32ull * YSTRIDE, gyt);
    {
        GemmSet s = {{Wc, nullptr, nullptr}, {bc, nullptr, nullptr},
                     {gx2, nullptr, nullptr}, {gtmp, nullptr, nullptr}};
        gemm_tc_kernel<true><<<dim3(50, 8, 1), 128>>>(gyt, s);
    }
    ln_kernel<<<M1 / 8, 256>>>(gtmp, g3, b3, out, M1);
}